// round 6
// baseline (speedup 1.0000x reference)
#include <cuda_runtime.h>
#include <cuda_bf16.h>
#include <math.h>
#include <stdint.h>

#define NTOK 1024
#define CDIM 64
#define BATCH 2
#define SS (NTOK*NTOK)
#define KSEL (SS/6)   /* 174762 */

// ---------------- device scratch (no allocations allowed) ----------------
__device__ float g_mean[BATCH*NTOK];
__device__ float g_std[BATCH*NTOK];
__device__ __nv_bfloat16 g_e0[BATCH*SS], g_e1[BATCH*SS], g_e2[BATCH*SS];
__device__ __nv_bfloat16 g_h0[BATCH*SS], g_h1[BATCH*SS], g_h2[BATCH*SS];
__device__ __nv_bfloat16 g_r0[BATCH*SS], g_r1[BATCH*SS], g_r2[BATCH*SS];
__device__ __nv_bfloat16 g_a0[BATCH*SS], g_a1[BATCH*SS], g_a2[BATCH*SS];
__device__ float g_L[BATCH*SS];
__device__ float g_W[BATCH*SS];
__device__ unsigned g_h16[BATCH][65536];
__device__ unsigned long long g_cand[BATCH][65536];
struct Sel2 { unsigned P, kneed, T, idxT, ncand; };
__device__ Sel2 g_s2[BATCH];

__device__ __forceinline__ unsigned fkey(float f) {
    unsigned u = __float_as_uint(f);
    return (u & 0x80000000u) ? ~u : (u | 0x80000000u);
}

__device__ __forceinline__ void split3(float v, __nv_bfloat16* p0,
                                       __nv_bfloat16* p1, __nv_bfloat16* p2) {
    __nv_bfloat16 b0 = __float2bfloat16(v);
    float r = v - __bfloat162float(b0);
    __nv_bfloat16 b1 = __float2bfloat16(r);
    float r2 = r - __bfloat162float(b1);
    *p0 = b0; *p1 = b1; *p2 = __float2bfloat16(r2);
}

__device__ __forceinline__ uint32_t s2u(const void* p) {
    uint32_t a;
    asm("{ .reg .u64 t; cvta.to.shared.u64 t, %1; cvt.u32.u64 %0, t; }" : "=r"(a) : "l"(p));
    return a;
}

// ---------------- row stats ----------------
__global__ void row_stats(const float* __restrict__ x) {
    int warp = threadIdx.x >> 5, lane = threadIdx.x & 31;
    int row = blockIdx.x * 8 + warp;
    const float* xr = x + (size_t)row * CDIM;
    float v0 = xr[lane], v1 = xr[lane + 32];
    float s = v0 + v1;
    #pragma unroll
    for (int o = 16; o; o >>= 1) s += __shfl_xor_sync(0xFFFFFFFFu, s, o);
    float mean = s * (1.0f / CDIM);
    float d0 = v0 - mean, d1 = v1 - mean;
    float ss = d0 * d0 + d1 * d1;
    #pragma unroll
    for (int o = 16; o; o >>= 1) ss += __shfl_xor_sync(0xFFFFFFFFu, ss, o);
    if (lane == 0) { g_mean[row] = mean; g_std[row] = sqrtf(ss); }
}

// ---------------- fused pairwise (upper triangle only) -> bf16 splits ----------------
__global__ __launch_bounds__(256) void pairwise(const float* __restrict__ x) {
    __shared__ float xi[32][CDIM + 1];
    __shared__ float xj[32][CDIM + 1];
    __shared__ float smi[32], ssi[32], smj[32], ssj[32];
    __shared__ __nv_bfloat16 tb[32][33];
    int b = blockIdx.z;
    // triangular decode: block t -> (bi, bj), bi <= bj
    int t = blockIdx.x;
    int bi = (int)((65.0f - sqrtf(4225.0f - 8.0f * (float)t)) * 0.5f);
    while (32*bi - bi*(bi-1)/2 > t) bi--;
    while (32*(bi+1) - (bi+1)*bi/2 <= t) bi++;
    int bj = bi + (t - (32*bi - bi*(bi-1)/2));
    int i0 = bi * 32, j0 = bj * 32;

    const float* xb = x + (size_t)b * NTOK * CDIM;
    int tid = threadIdx.x;
    for (int l = tid; l < 32 * CDIM; l += 256) {
        int r = l >> 6, c = l & 63;
        xi[r][c] = xb[(size_t)(i0 + r) * CDIM + c];
        xj[r][c] = xb[(size_t)(j0 + r) * CDIM + c];
    }
    if (tid < 32)      { smi[tid] = g_mean[b*NTOK + i0 + tid]; ssi[tid] = g_std[b*NTOK + i0 + tid]; }
    else if (tid < 64) { int tt = tid - 32; smj[tt] = g_mean[b*NTOK + j0 + tt]; ssj[tt] = g_std[b*NTOK + j0 + tt]; }
    __syncthreads();

    int tx = tid & 15, ty = tid >> 4;
    int r0 = ty * 2, r1 = ty * 2 + 1;
    int c0 = tx, c1 = tx + 16;

    float ssq[2][2] = {{0,0},{0,0}};
    float mx[2][2]  = {{0,0},{0,0}};
    float dt[2][2]  = {{0,0},{0,0}};
    float mi0 = smi[r0], mi1 = smi[r1], mj0 = smj[c0], mj1 = smj[c1];

    #pragma unroll 16
    for (int c = 0; c < CDIM; c++) {
        float a0 = xi[r0][c], a1 = xi[r1][c];
        float b0 = xj[c0][c], b1 = xj[c1][c];
        float ac0 = a0 - mi0, ac1 = a1 - mi1;
        float bc0 = b0 - mj0, bc1 = b1 - mj1;
        float d;
        d = a0 - b0; ssq[0][0] = fmaf(d,d,ssq[0][0]); mx[0][0] = fmaxf(mx[0][0], fabsf(d)); dt[0][0] = fmaf(ac0,bc0,dt[0][0]);
        d = a0 - b1; ssq[0][1] = fmaf(d,d,ssq[0][1]); mx[0][1] = fmaxf(mx[0][1], fabsf(d)); dt[0][1] = fmaf(ac0,bc1,dt[0][1]);
        d = a1 - b0; ssq[1][0] = fmaf(d,d,ssq[1][0]); mx[1][0] = fmaxf(mx[1][0], fabsf(d)); dt[1][0] = fmaf(ac1,bc0,dt[1][0]);
        d = a1 - b1; ssq[1][1] = fmaf(d,d,ssq[1][1]); mx[1][1] = fmaxf(mx[1][1], fabsf(d)); dt[1][1] = fmaf(ac1,bc1,dt[1][1]);
    }

    size_t boff = (size_t)b * SS;
    __nv_bfloat16* Gm[9] = { g_e0+boff, g_e1+boff, g_e2+boff,
                             g_h0+boff, g_h1+boff, g_h2+boff,
                             g_r0+boff, g_r1+boff, g_r2+boff };
    __nv_bfloat16 sv[9][2][2];
    #pragma unroll
    for (int p = 0; p < 2; p++) {
        float si = ssi[r0 + p];
        #pragma unroll
        for (int q = 0; q < 2; q++) {
            split3(sqrtf(ssq[p][q]), &sv[0][p][q], &sv[1][p][q], &sv[2][p][q]);
            split3(mx[p][q],         &sv[3][p][q], &sv[4][p][q], &sv[5][p][q]);
            float cr = dt[p][q] / (si * ssj[(q==0)?c0:c1]);
            cr = fminf(fmaxf(cr, -1.0f), 1.0f);
            split3(cr, &sv[6][p][q], &sv[7][p][q], &sv[8][p][q]);
        }
    }
    // direct writes (I, J)
    #pragma unroll
    for (int m = 0; m < 9; m++) {
        #pragma unroll
        for (int p = 0; p < 2; p++) {
            #pragma unroll
            for (int q = 0; q < 2; q++) {
                int I = i0 + r0 + p;
                int J = j0 + ((q == 0) ? c0 : c1);
                Gm[m][(size_t)I * NTOK + J] = sv[m][p][q];
            }
        }
    }
    // transposed writes (J, I) via smem staging
    if (bi != bj) {
        int wr = tid >> 3, wc = (tid & 7) * 4;
        #pragma unroll
        for (int m = 0; m < 9; m++) {
            __syncthreads();
            tb[c0][r0] = sv[m][0][0]; tb[c0][r1] = sv[m][1][0];
            tb[c1][r0] = sv[m][0][1]; tb[c1][r1] = sv[m][1][1];
            __syncthreads();
            __nv_bfloat16 w0 = tb[wr][wc], w1 = tb[wr][wc+1], w2 = tb[wr][wc+2], w3 = tb[wr][wc+3];
            unsigned lo = ((unsigned)__bfloat16_as_ushort(w1) << 16) | __bfloat16_as_ushort(w0);
            unsigned hi = ((unsigned)__bfloat16_as_ushort(w3) << 16) | __bfloat16_as_ushort(w2);
            *(uint2*)(Gm[m] + (size_t)(j0 + wr) * NTOK + i0 + wc) = make_uint2(lo, hi);
        }
    }
}

// ---------------- bf16x6 GEMM via mma.sync (HMMA): D = A * B^T ----------------
#define KC 32
#define ROWB 80
#define TILEB (128*ROWB)
#define STAGEB (6*TILEB)
#define GSMEM (2*STAGEB)

#define LDSM4(r, a) \
    asm volatile("ldmatrix.sync.aligned.m8n8.x4.shared.b16 {%0,%1,%2,%3}, [%4];" \
        : "=r"((r)[0]), "=r"((r)[1]), "=r"((r)[2]), "=r"((r)[3]) : "r"(a))

#define MMA16816(d, a, b0r, b1r) \
    asm volatile("mma.sync.aligned.m16n8k16.row.col.f32.bf16.bf16.f32 " \
        "{%0,%1,%2,%3}, {%4,%5,%6,%7}, {%8,%9}, {%0,%1,%2,%3};" \
        : "+f"((d)[0]), "+f"((d)[1]), "+f"((d)[2]), "+f"((d)[3]) \
        : "r"((a)[0]), "r"((a)[1]), "r"((a)[2]), "r"((a)[3]), "r"(b0r), "r"(b1r))

__global__ __launch_bounds__(512, 1) void gemm_mma(int which) {
    extern __shared__ __align__(128) char dsm[];
    uint32_t sb = s2u(dsm);
    int tid = threadIdx.x, lane = tid & 31, wid = tid >> 5;
    int wm = wid >> 2, wn = wid & 3;   // warp grid 4x4, warp tile 32x32
    size_t boff = (size_t)blockIdx.z * SS;
    const __nv_bfloat16* mats[6];
    if (which == 0) {
        mats[0]=g_e0+boff; mats[1]=g_e1+boff; mats[2]=g_e2+boff;
        mats[3]=g_h0+boff; mats[4]=g_h1+boff; mats[5]=g_h2+boff;
    } else {
        mats[0]=g_a0+boff; mats[1]=g_a1+boff; mats[2]=g_a2+boff;
        mats[3]=g_r0+boff; mats[4]=g_r1+boff; mats[5]=g_r2+boff;
    }
    float* C = (which == 0 ? g_L : g_W) + boff;
    int rowBase = blockIdx.y * 128, colBase = blockIdx.x * 128;

    float acc[2][4][4];
    #pragma unroll
    for (int i = 0; i < 2; i++)
        #pragma unroll
        for (int j = 0; j < 4; j++)
            #pragma unroll
            for (int k = 0; k < 4; k++) acc[i][j][k] = 0.0f;

    unsigned aRowOff = (unsigned)(wm*32 + (lane & 15)) * ROWB + ((lane >> 4) << 4);
    unsigned bRowOff = (unsigned)(wn*32 + (lane & 7) + ((lane >> 4) << 3)) * ROWB
                     + (((lane >> 3) & 1) << 4);

#define LOADSTAGE(st, k0) do { \
    unsigned _so = sb + (unsigned)(st)*STAGEB; \
    _Pragma("unroll") \
    for (int i = 0; i < 6; i++) { \
        int idx = ((i << 9) + tid) & 511; \
        int row = idx >> 2, c8 = idx & 3; \
        int rb = (i < 3) ? rowBase : colBase; \
        const __nv_bfloat16* gp = mats[i] + (size_t)(rb + row) * NTOK + (k0) + c8*8; \
        unsigned sa = _so + i*TILEB + row*ROWB + c8*16; \
        asm volatile("cp.async.cg.shared.global [%0], [%1], 16;" :: "r"(sa), "l"(gp)); \
    } \
    asm volatile("cp.async.commit_group;"); \
} while(0)

    LOADSTAGE(0, 0);

    const int pa[6] = {0,0,1,0,1,2}, pb[6] = {0,1,0,2,1,0};

    for (int t = 0; t < 32; t++) {
        if (t < 31) {
            LOADSTAGE((t + 1) & 1, (t + 1) * KC);
            asm volatile("cp.async.wait_group 1;");
        } else {
            asm volatile("cp.async.wait_group 0;");
        }
        __syncthreads();
        unsigned stoff = sb + (unsigned)(t & 1) * STAGEB;
        #pragma unroll
        for (int kf = 0; kf < 2; kf++) {
            uint32_t af[3][2][4];
            #pragma unroll
            for (int s = 0; s < 3; s++)
                #pragma unroll
                for (int mf = 0; mf < 2; mf++)
                    LDSM4(af[s][mf], stoff + s*TILEB + aRowOff + mf*(16*ROWB) + kf*32);
            uint32_t bf[3][2][4];
            #pragma unroll
            for (int s = 0; s < 3; s++)
                #pragma unroll
                for (int np = 0; np < 2; np++)
                    LDSM4(bf[s][np], stoff + (3+s)*TILEB + bRowOff + np*(16*ROWB) + kf*32);
            #pragma unroll
            for (int p = 0; p < 6; p++) {
                int sa = pa[p], sbp = pb[p];
                #pragma unroll
                for (int mf = 0; mf < 2; mf++) {
                    #pragma unroll
                    for (int np = 0; np < 2; np++) {
                        MMA16816(acc[mf][2*np],   af[sa][mf], bf[sbp][np][0], bf[sbp][np][1]);
                        MMA16816(acc[mf][2*np+1], af[sa][mf], bf[sbp][np][2], bf[sbp][np][3]);
                    }
                }
            }
        }
        __syncthreads();
    }

    int r0 = rowBase + wm * 32 + (lane >> 2);
    int c0 = colBase + wn * 32 + (lane & 3) * 2;
    #pragma unroll
    for (int mf = 0; mf < 2; mf++) {
        #pragma unroll
        for (int nb = 0; nb < 4; nb++) {
            float* base = C + (size_t)(r0 + mf * 16) * NTOK + c0 + nb * 8;
            *(float2*)base = make_float2(acc[mf][nb][0], acc[mf][nb][1]);
            *(float2*)(base + 8 * NTOK) = make_float2(acc[mf][nb][2], acc[mf][nb][3]);
        }
    }
#undef LOADSTAGE
}

// ---------------- row softmax of 0.125*L -> attn bf16 splits ----------------
__global__ void softmax_rows() {
    int b = blockIdx.y, row = blockIdx.x;
    size_t base = (size_t)b * SS + (size_t)row * NTOK;
    float* L = g_L + base;
    int tid = threadIdx.x;  // 256
    float v[4];
    #pragma unroll
    for (int i = 0; i < 4; i++) v[i] = L[tid + i * 256] * 0.125f;
    float m = fmaxf(fmaxf(v[0], v[1]), fmaxf(v[2], v[3]));
    __shared__ float red[256];
    red[tid] = m; __syncthreads();
    for (int s = 128; s; s >>= 1) { if (tid < s) red[tid] = fmaxf(red[tid], red[tid + s]); __syncthreads(); }
    m = red[0]; __syncthreads();
    float e[4], sm = 0.0f;
    #pragma unroll
    for (int i = 0; i < 4; i++) { e[i] = expf(v[i] - m); sm += e[i]; }
    red[tid] = sm; __syncthreads();
    for (int s = 128; s; s >>= 1) { if (tid < s) red[tid] += red[tid + s]; __syncthreads(); }
    sm = red[0];
    #pragma unroll
    for (int i = 0; i < 4; i++) {
        size_t o = base + tid + i * 256;
        split3(e[i] / sm, g_a0 + o, g_a1 + o, g_a2 + o);
    }
}

// ---------------- top-k selection (16-bit radix + candidate gather) ----------------
__global__ void sel2_zero() {
    int i = blockIdx.x * 1024 + threadIdx.x;
    ((unsigned*)g_h16)[i] = 0;
    if (i < BATCH) g_s2[i].ncand = 0;
}

__global__ void sel2_hist() {
    int b = blockIdx.y;
    const float* W = g_W + (size_t)b * SS;
    for (int i = blockIdx.x * blockDim.x + threadIdx.x; i < SS; i += gridDim.x * blockDim.x)
        atomicAdd(&g_h16[b][fkey(W[i]) >> 16], 1u);
}

__global__ void sel2_scan() {   // 1 block of 256 per batch
    int b = blockIdx.x, tid = threadIdx.x;
    __shared__ unsigned csum[256];
    unsigned s = 0;
    for (int k = 0; k < 256; k++) s += g_h16[b][tid * 256 + k];
    csum[tid] = s;
    __syncthreads();
    if (tid == 0) {
        unsigned acc = 0; int c = 255;
        for (; c >= 0; c--) { if (acc + csum[c] >= (unsigned)KSEL) break; acc += csum[c]; }
        int bin = c * 256 + 255;
        for (;; bin--) { unsigned ct = g_h16[b][bin]; if (acc + ct >= (unsigned)KSEL) break; acc += ct; }
        g_s2[b].P = (unsigned)bin;
        g_s2[b].kneed = (unsigned)KSEL - acc;
    }
}

__global__ void sel2_gather() {
    int b = blockIdx.y;
    unsigned P = g_s2[b].P;
    const float* W = g_W + (size_t)b * SS;
    for (int i = blockIdx.x * blockDim.x + threadIdx.x; i < SS; i += gridDim.x * blockDim.x) {
        unsigned u = fkey(W[i]);
        if ((u >> 16) == P) {
            unsigned pos = atomicAdd(&g_s2[b].ncand, 1u);
            if (pos < 65536u)
                g_cand[b][pos] = ((unsigned long long)u << 32) | (unsigned)i;
        }
    }
}

__global__ void sel2_finish() {  // 1 block of 1024 per batch
    int b = blockIdx.x, tid = threadIdx.x;
    __shared__ unsigned h[256];
    __shared__ unsigned s_prefix, s_kneed;
    unsigned n = g_s2[b].ncand; if (n > 65536u) n = 65536u;
    if (tid == 0) { s_prefix = 0; s_kneed = g_s2[b].kneed; }
    __syncthreads();
    // radix select kneed-th largest low-16 key among candidates (2 levels)
    #pragma unroll
    for (int lvl = 0; lvl < 2; lvl++) {
        int shift = 8 - 8 * lvl;
        unsigned pmask = (lvl == 0) ? 0u : 0xFF00u;
        if (tid < 256) h[tid] = 0;
        __syncthreads();
        unsigned pfx = s_prefix;
        for (unsigned i = tid; i < n; i += 1024) {
            unsigned low = (unsigned)(g_cand[b][i] >> 32) & 0xFFFFu;
            if ((low & pmask) == pfx) atomicAdd(&h[(low >> shift) & 255], 1u);
        }
        __syncthreads();
        if (tid == 0) {
            unsigned kneed = s_kneed;
            int bin = 255;
            for (; bin >= 0; bin--) { if (kneed <= h[bin]) break; kneed -= h[bin]; }
            s_prefix = pfx | ((unsigned)bin << shift);
            s_kneed = kneed;
        }
        __syncthreads();
    }
    unsigned T = (g_s2[b].P << 16) | s_prefix;
    // radix select kneed-th largest idx among exact-T ties (idx < 2^20, 3 levels)
    if (tid == 0) s_prefix = 0;
    __syncthreads();
    #pragma unroll
    for (int lvl = 0; lvl < 3; lvl++) {
        int shift = 16 - 8 * lvl;
        unsigned pmask = ~((1u << (shift + 8)) - 1u);
        if (tid < 256) h[tid] = 0;
        __syncthreads();
        unsigned pfx = s_prefix;
        for (unsigned i = tid; i < n; i += 1024) {
            unsigned long long cv = g_cand[b][i];
            unsigned key = (unsigned)(cv >> 32);
            unsigned idx = (unsigned)cv;
            if (key == T && (idx & pmask) == pfx) atomicAdd(&h[(idx >> shift) & 255], 1u);
        }
        __syncthreads();
        if (tid == 0) {
            unsigned kneed = s_kneed;
            int bin = 255;
            for (; bin >= 0; bin--) { if (kneed <= h[bin]) break; kneed -= h[bin]; }
            s_prefix = pfx | ((unsigned)bin << shift);
            s_kneed = kneed;
        }
        __syncthreads();
    }
    if (tid == 0) { g_s2[b].T = T; g_s2[b].idxT = s_prefix; }
}

__global__ void mask_write(float* __restrict__ out) {
    int b = blockIdx.y;
    int idx = blockIdx.x * blockDim.x + threadIdx.x;
    unsigned T = g_s2[b].T;
    unsigned idxT = g_s2[b].idxT;
    unsigned u = fkey(g_W[(size_t)b * SS + idx]);
    float v = (u > T || (u == T && (unsigned)idx >= idxT)) ? 1.0f : 0.0f;
    out[(size_t)b * SS + idx] = v;
}

// ---------------- launcher ----------------
extern "C" void kernel_launch(void* const* d_in, const int* in_sizes, int n_in,
                              void* d_out, int out_size) {
    const float* x = (const float*)d_in[0];
    float* out = (float*)d_out;

    cudaFuncSetAttribute(gemm_mma, cudaFuncAttributeMaxDynamicSharedMemorySize, GSMEM);

    row_stats<<<(BATCH * NTOK) / 8, 256>>>(x);
    pairwise<<<dim3(528, 1, BATCH), 256>>>(x);
    gemm_mma<<<dim3(8, 8, BATCH), 512, GSMEM>>>(0);
    softmax_rows<<<dim3(NTOK, BATCH), 256>>>();
    gemm_mma<<<dim3(8, 8, BATCH), 512, GSMEM>>>(1);

    sel2_zero<<<(BATCH * 65536) / 1024, 1024>>>();
    sel2_hist<<<dim3(128, BATCH), 256>>>();
    sel2_scan<<<BATCH, 256>>>();
    sel2_gather<<<dim3(128, BATCH), 256>>>();
    sel2_finish<<<BATCH, 1024>>>();
    mask_write<<<dim3(NTOK, BATCH), 1024>>>(out);
}

// round 7
// speedup vs baseline: 1.0632x; 1.0632x over previous
#include <cuda_runtime.h>
#include <cuda_fp16.h>
#include <math.h>
#include <stdint.h>

#define NTOK 1024
#define CDIM 64
#define BATCH 2
#define SS (NTOK*NTOK)
#define KSEL (SS/6)   /* 174762 */

// ---------------- device scratch ----------------
__device__ float g_mean[BATCH*NTOK];
__device__ float g_std[BATCH*NTOK];
// fp16 2-way splits
__device__ __half g_e0[BATCH*SS], g_e1[BATCH*SS];   // euclidean  (A of gemm1)
__device__ __half g_h0[BATCH*SS], g_h1[BATCH*SS];   // chebyshev  (B of gemm1)
__device__ __half g_r0[BATCH*SS], g_r1[BATCH*SS];   // corrcoef   (B of gemm2)
__device__ __half g_a0[BATCH*SS], g_a1[BATCH*SS];   // attn       (A of gemm2)
__device__ float g_L[BATCH*SS];
__device__ float g_W[BATCH*SS];
__device__ unsigned g_hist[BATCH][256];
struct SelState { unsigned prefix, kneed, T, ct, idxT, tiecount; };
__device__ SelState g_sel[BATCH];
__device__ int g_ties[BATCH*SS];

__device__ __forceinline__ unsigned fkey(float f) {
    unsigned u = __float_as_uint(f);
    return (u & 0x80000000u) ? ~u : (u | 0x80000000u);
}

// 2-way fp16 split: v ~= h0 + h1
__device__ __forceinline__ void split2h(float v, __half* p0, __half* p1) {
    __half h0 = __float2half_rn(v);
    float r = v - __half2float(h0);
    *p0 = h0; *p1 = __float2half_rn(r);
}

__device__ __forceinline__ uint32_t s2u(const void* p) {
    uint32_t a;
    asm("{ .reg .u64 t; cvta.to.shared.u64 t, %1; cvt.u32.u64 %0, t; }" : "=r"(a) : "l"(p));
    return a;
}

// ---------------- row stats ----------------
__global__ void row_stats(const float* __restrict__ x) {
    int warp = threadIdx.x >> 5, lane = threadIdx.x & 31;
    int row = blockIdx.x * 8 + warp;
    const float* xr = x + (size_t)row * CDIM;
    float v0 = xr[lane], v1 = xr[lane + 32];
    float s = v0 + v1;
    #pragma unroll
    for (int o = 16; o; o >>= 1) s += __shfl_xor_sync(0xFFFFFFFFu, s, o);
    float mean = s * (1.0f / CDIM);
    float d0 = v0 - mean, d1 = v1 - mean;
    float ss = d0 * d0 + d1 * d1;
    #pragma unroll
    for (int o = 16; o; o >>= 1) ss += __shfl_xor_sync(0xFFFFFFFFu, ss, o);
    if (lane == 0) { g_mean[row] = mean; g_std[row] = sqrtf(ss); }
}

// ---------------- fused pairwise -> fp16 splits (full grid, round-5 style) ----------------
__global__ __launch_bounds__(256) void pairwise(const float* __restrict__ x) {
    __shared__ float xi[32][CDIM + 1];
    __shared__ float xj[32][CDIM + 1];
    __shared__ float smi[32], ssi[32], smj[32], ssj[32];
    int b = blockIdx.z;
    int i0 = blockIdx.y * 32, j0 = blockIdx.x * 32;
    const float* xb = x + (size_t)b * NTOK * CDIM;
    int tid = threadIdx.x;
    for (int l = tid; l < 32 * CDIM; l += 256) {
        int r = l >> 6, c = l & 63;
        xi[r][c] = xb[(size_t)(i0 + r) * CDIM + c];
        xj[r][c] = xb[(size_t)(j0 + r) * CDIM + c];
    }
    if (tid < 32)      { smi[tid] = g_mean[b*NTOK + i0 + tid]; ssi[tid] = g_std[b*NTOK + i0 + tid]; }
    else if (tid < 64) { int t = tid - 32; smj[t] = g_mean[b*NTOK + j0 + t]; ssj[t] = g_std[b*NTOK + j0 + t]; }
    __syncthreads();

    int tx = tid & 15, ty = tid >> 4;
    int r0 = ty * 2, r1 = ty * 2 + 1;
    int c0 = tx, c1 = tx + 16;

    float ssq[2][2] = {{0,0},{0,0}};
    float mx[2][2]  = {{0,0},{0,0}};
    float dt[2][2]  = {{0,0},{0,0}};
    float mi0 = smi[r0], mi1 = smi[r1], mj0 = smj[c0], mj1 = smj[c1];

    #pragma unroll 16
    for (int c = 0; c < CDIM; c++) {
        float a0 = xi[r0][c], a1 = xi[r1][c];
        float b0 = xj[c0][c], b1 = xj[c1][c];
        float ac0 = a0 - mi0, ac1 = a1 - mi1;
        float bc0 = b0 - mj0, bc1 = b1 - mj1;
        float d;
        d = a0 - b0; ssq[0][0] = fmaf(d,d,ssq[0][0]); mx[0][0] = fmaxf(mx[0][0], fabsf(d)); dt[0][0] = fmaf(ac0,bc0,dt[0][0]);
        d = a0 - b1; ssq[0][1] = fmaf(d,d,ssq[0][1]); mx[0][1] = fmaxf(mx[0][1], fabsf(d)); dt[0][1] = fmaf(ac0,bc1,dt[0][1]);
        d = a1 - b0; ssq[1][0] = fmaf(d,d,ssq[1][0]); mx[1][0] = fmaxf(mx[1][0], fabsf(d)); dt[1][0] = fmaf(ac1,bc0,dt[1][0]);
        d = a1 - b1; ssq[1][1] = fmaf(d,d,ssq[1][1]); mx[1][1] = fmaxf(mx[1][1], fabsf(d)); dt[1][1] = fmaf(ac1,bc1,dt[1][1]);
    }
    #pragma unroll
    for (int p = 0; p < 2; p++) {
        int I = i0 + r0 + p;
        float si = ssi[r0 + p];
        #pragma unroll
        for (int q = 0; q < 2; q++) {
            int J = j0 + ((q == 0) ? c0 : c1);
            size_t o = (size_t)b * SS + (size_t)I * NTOK + J;
            split2h(sqrtf(ssq[p][q]), g_e0 + o, g_e1 + o);
            split2h(mx[p][q],         g_h0 + o, g_h1 + o);
            float cr = dt[p][q] / (si * ssj[(q==0)?c0:c1]);
            cr = fminf(fmaxf(cr, -1.0f), 1.0f);
            split2h(cr, g_r0 + o, g_r1 + o);
        }
    }
}

// ---------------- fp16x3 GEMM via mma.sync (HMMA): D = A * B^T ----------------
// D = (A0+A1)(B0+B1)^T ~= A0B0 + A0B1 + A1B0  (A1B1 ~ 2^-24, dropped)
#define KC 32
#define ROWB 80
#define TILEB (128*ROWB)       /* 10240 */
#define STAGEB (4*TILEB)       /* 40960 */
#define GSMEM (2*STAGEB)       /* 81920 */

#define LDSM4(r, a) \
    asm volatile("ldmatrix.sync.aligned.m8n8.x4.shared.b16 {%0,%1,%2,%3}, [%4];" \
        : "=r"((r)[0]), "=r"((r)[1]), "=r"((r)[2]), "=r"((r)[3]) : "r"(a))

#define MMA16816(d, a, b0r, b1r) \
    asm volatile("mma.sync.aligned.m16n8k16.row.col.f32.f16.f16.f32 " \
        "{%0,%1,%2,%3}, {%4,%5,%6,%7}, {%8,%9}, {%0,%1,%2,%3};" \
        : "+f"((d)[0]), "+f"((d)[1]), "+f"((d)[2]), "+f"((d)[3]) \
        : "r"((a)[0]), "r"((a)[1]), "r"((a)[2]), "r"((a)[3]), "r"(b0r), "r"(b1r))

__global__ __launch_bounds__(256, 1) void gemm_mma(int which) {
    extern __shared__ __align__(128) char dsm[];
    uint32_t sb = s2u(dsm);
    int tid = threadIdx.x, lane = tid & 31, wid = tid >> 5;
    int wm = wid >> 2, wn = wid & 3;   // warp grid 2x4, warp tile 64x32
    size_t boff = (size_t)blockIdx.z * SS;
    const __half* mats[4];
    if (which == 0) { mats[0]=g_e0+boff; mats[1]=g_e1+boff; mats[2]=g_h0+boff; mats[3]=g_h1+boff; }
    else            { mats[0]=g_a0+boff; mats[1]=g_a1+boff; mats[2]=g_r0+boff; mats[3]=g_r1+boff; }
    float* C = (which == 0 ? g_L : g_W) + boff;
    int rowBase = blockIdx.y * 128, colBase = blockIdx.x * 128;

    float acc[4][4][4];
    #pragma unroll
    for (int i = 0; i < 4; i++)
        #pragma unroll
        for (int j = 0; j < 4; j++)
            #pragma unroll
            for (int k = 0; k < 4; k++) acc[i][j][k] = 0.0f;

    unsigned aRowOff = (unsigned)(wm*64 + (lane & 15)) * ROWB + ((lane >> 4) << 4);
    unsigned bRowOff = (unsigned)(wn*32 + (lane & 7) + ((lane >> 4) << 3)) * ROWB
                     + (((lane >> 3) & 1) << 4);

#define LOADSTAGE(st, k0) do { \
    unsigned _so = sb + (unsigned)(st)*STAGEB; \
    _Pragma("unroll") \
    for (int i = 0; i < 8; i++) { \
        int g = i * 256 + tid; \
        int mat = g >> 9, idx = g & 511; \
        int row = idx >> 2, c8 = idx & 3; \
        int rb = (mat < 2) ? rowBase : colBase; \
        const __half* gp = mats[mat] + (size_t)(rb + row) * NTOK + (k0) + c8*8; \
        unsigned sa = _so + mat*TILEB + row*ROWB + c8*16; \
        asm volatile("cp.async.cg.shared.global [%0], [%1], 16;" :: "r"(sa), "l"(gp)); \
    } \
    asm volatile("cp.async.commit_group;"); \
} while(0)

    LOADSTAGE(0, 0);

    for (int t = 0; t < 32; t++) {
        if (t < 31) {
            LOADSTAGE((t + 1) & 1, (t + 1) * KC);
            asm volatile("cp.async.wait_group 1;");
        } else {
            asm volatile("cp.async.wait_group 0;");
        }
        __syncthreads();
        unsigned stoff = sb + (unsigned)(t & 1) * STAGEB;
        #pragma unroll
        for (int kf = 0; kf < 2; kf++) {
            uint32_t af[2][4][4];
            #pragma unroll
            for (int s = 0; s < 2; s++)
                #pragma unroll
                for (int mf = 0; mf < 4; mf++)
                    LDSM4(af[s][mf], stoff + s*TILEB + aRowOff + mf*(16*ROWB) + kf*32);
            uint32_t bf[2][2][4];
            #pragma unroll
            for (int s = 0; s < 2; s++)
                #pragma unroll
                for (int np = 0; np < 2; np++)
                    LDSM4(bf[s][np], stoff + (2+s)*TILEB + bRowOff + np*(16*ROWB) + kf*32);
            // products: (A0,B0), (A0,B1), (A1,B0)
            #pragma unroll
            for (int p = 0; p < 3; p++) {
                int sa = (p == 2) ? 1 : 0;
                int sbp = (p == 1) ? 1 : 0;
                #pragma unroll
                for (int mf = 0; mf < 4; mf++) {
                    MMA16816(acc[mf][0], af[sa][mf], bf[sbp][0][0], bf[sbp][0][1]);
                    MMA16816(acc[mf][1], af[sa][mf], bf[sbp][0][2], bf[sbp][0][3]);
                    MMA16816(acc[mf][2], af[sa][mf], bf[sbp][1][0], bf[sbp][1][1]);
                    MMA16816(acc[mf][3], af[sa][mf], bf[sbp][1][2], bf[sbp][1][3]);
                }
            }
        }
        __syncthreads();
    }

    int r0 = rowBase + wm * 64 + (lane >> 2);
    int c0 = colBase + wn * 32 + (lane & 3) * 2;
    #pragma unroll
    for (int mf = 0; mf < 4; mf++) {
        #pragma unroll
        for (int nb = 0; nb < 4; nb++) {
            float* base = C + (size_t)(r0 + mf * 16) * NTOK + c0 + nb * 8;
            *(float2*)base = make_float2(acc[mf][nb][0], acc[mf][nb][1]);
            *(float2*)(base + 8 * NTOK) = make_float2(acc[mf][nb][2], acc[mf][nb][3]);
        }
    }
#undef LOADSTAGE
}

// ---------------- row softmax of 0.125*L -> attn fp16 splits ----------------
__global__ void softmax_rows() {
    int b = blockIdx.y, row = blockIdx.x;
    size_t base = (size_t)b * SS + (size_t)row * NTOK;
    float* L = g_L + base;
    int tid = threadIdx.x;  // 256
    float v[4];
    #pragma unroll
    for (int i = 0; i < 4; i++) v[i] = L[tid + i * 256] * 0.125f;
    float m = fmaxf(fmaxf(v[0], v[1]), fmaxf(v[2], v[3]));
    __shared__ float red[256];
    red[tid] = m; __syncthreads();
    for (int s = 128; s; s >>= 1) { if (tid < s) red[tid] = fmaxf(red[tid], red[tid + s]); __syncthreads(); }
    m = red[0]; __syncthreads();
    float e[4], sm = 0.0f;
    #pragma unroll
    for (int i = 0; i < 4; i++) { e[i] = expf(v[i] - m); sm += e[i]; }
    red[tid] = sm; __syncthreads();
    for (int s = 128; s; s >>= 1) { if (tid < s) red[tid] += red[tid + s]; __syncthreads(); }
    sm = red[0];
    #pragma unroll
    for (int i = 0; i < 4; i++) {
        size_t o = base + tid + i * 256;
        split2h(e[i] / sm, g_a0 + o, g_a1 + o);
    }
}

// ---------------- top-k radix select (round-5 proven version) ----------------
__global__ void sel_init() {
    int b = blockIdx.x;
    for (int i = threadIdx.x; i < 256; i += blockDim.x) g_hist[b][i] = 0;
    if (threadIdx.x == 0) {
        g_sel[b].prefix = 0; g_sel[b].kneed = KSEL; g_sel[b].T = 0;
        g_sel[b].ct = 0; g_sel[b].idxT = 0; g_sel[b].tiecount = 0;
    }
}

__global__ void sel_hist(int level) {
    int b = blockIdx.y;
    __shared__ unsigned h[256];
    for (int i = threadIdx.x; i < 256; i += blockDim.x) h[i] = 0;
    __syncthreads();
    unsigned prefix = g_sel[b].prefix;
    int shift = 24 - 8 * level;
    unsigned pmask = (level == 0) ? 0u : (0xFFFFFFFFu << (shift + 8));
    const float* W = g_W + (size_t)b * SS;
    for (int i = blockIdx.x * blockDim.x + threadIdx.x; i < SS; i += gridDim.x * blockDim.x) {
        unsigned u = fkey(W[i]);
        if ((u & pmask) == prefix) atomicAdd(&h[(u >> shift) & 255], 1u);
    }
    __syncthreads();
    for (int i = threadIdx.x; i < 256; i += blockDim.x)
        if (h[i]) atomicAdd(&g_hist[b][i], h[i]);
}

__global__ void sel_scan(int level) {
    int b = blockIdx.x;
    SelState& st = g_sel[b];
    int shift = 24 - 8 * level;
    unsigned kneed = st.kneed;
    int sel = 0; unsigned cnt = 0;
    for (int bin = 255; bin >= 0; bin--) {
        unsigned c = g_hist[b][bin];
        if (kneed <= c) { sel = bin; cnt = c; break; }
        kneed -= c;
    }
    st.prefix |= ((unsigned)sel) << shift;
    st.kneed = kneed;
    if (level == 3) { st.T = st.prefix; st.ct = cnt; }
    for (int i = 0; i < 256; i++) g_hist[b][i] = 0;
}

__global__ void sel_gather() {
    int b = blockIdx.y;
    unsigned T = g_sel[b].T;
    const float* W = g_W + (size_t)b * SS;
    for (int i = blockIdx.x * blockDim.x + threadIdx.x; i < SS; i += gridDim.x * blockDim.x) {
        if (fkey(W[i]) == T) {
            unsigned pos = atomicAdd(&g_sel[b].tiecount, 1u);
            g_ties[(size_t)b * SS + pos] = i;
        }
    }
}

__global__ void sel_idx() {
    int b = blockIdx.x;
    __shared__ unsigned cnt;
    SelState& st = g_sel[b];
    unsigned ct = st.ct, need = st.kneed;
    if (need >= ct) { if (threadIdx.x == 0) st.idxT = 0; return; }
    const int* ties = g_ties + (size_t)b * SS;
    unsigned lo = 0, hi = SS - 1;
    for (int iter = 0; iter < 22; iter++) {
        if (lo >= hi) break;
        unsigned mid = (lo + hi + 1u) >> 1;
        if (threadIdx.x == 0) cnt = 0;
        __syncthreads();
        unsigned local = 0;
        for (unsigned i = threadIdx.x; i < ct; i += blockDim.x)
            local += (ties[i] >= (int)mid) ? 1u : 0u;
        if (local) atomicAdd(&cnt, local);
        __syncthreads();
        if (cnt >= need) lo = mid; else hi = mid - 1;
        __syncthreads();
    }
    if (threadIdx.x == 0) st.idxT = lo;
}

__global__ void mask_write(float* __restrict__ out) {
    int b = blockIdx.y;
    int idx = blockIdx.x * blockDim.x + threadIdx.x;
    unsigned T = g_sel[b].T;
    unsigned idxT = g_sel[b].idxT;
    unsigned u = fkey(g_W[(size_t)b * SS + idx]);
    float v = (u > T || (u == T && (unsigned)idx >= idxT)) ? 1.0f : 0.0f;
    out[(size_t)b * SS + idx] = v;
}

// ---------------- launcher ----------------
extern "C" void kernel_launch(void* const* d_in, const int* in_sizes, int n_in,
                              void* d_out, int out_size) {
    const float* x = (const float*)d_in[0];
    float* out = (float*)d_out;

    cudaFuncSetAttribute(gemm_mma, cudaFuncAttributeMaxDynamicSharedMemorySize, GSMEM);

    row_stats<<<(BATCH * NTOK) / 8, 256>>>(x);
    pairwise<<<dim3(32, 32, BATCH), 256>>>(x);
    gemm_mma<<<dim3(8, 8, BATCH), 256, GSMEM>>>(0);
    softmax_rows<<<dim3(NTOK, BATCH), 256>>>();
    gemm_mma<<<dim3(8, 8, BATCH), 256, GSMEM>>>(1);

    sel_init<<<BATCH, 256>>>();
    for (int level = 0; level < 4; level++) {
        sel_hist<<<dim3(128, BATCH), 256>>>(level);
        sel_scan<<<BATCH, 1>>>(level);
    }
    sel_gather<<<dim3(128, BATCH), 256>>>();
    sel_idx<<<BATCH, 1024>>>();
    mask_write<<<dim3(NTOK, BATCH), 1024>>>(out);
}

// round 8
// speedup vs baseline: 1.4075x; 1.3238x over previous
#include <cuda_runtime.h>
#include <cuda_bf16.h>
#include <math.h>
#include <stdint.h>

#define NTOK 1024
#define CDIM 64
#define BATCH 2
#define SS (NTOK*NTOK)
#define KSEL (SS/6)   /* 174762 */

// ---------------- device scratch (no allocations allowed) ----------------
__device__ float g_mean[BATCH*NTOK];
__device__ float g_std[BATCH*NTOK];
__device__ __nv_bfloat16 g_e0[BATCH*SS], g_e1[BATCH*SS], g_e2[BATCH*SS];
__device__ __nv_bfloat16 g_h0[BATCH*SS], g_h1[BATCH*SS], g_h2[BATCH*SS];
__device__ __nv_bfloat16 g_r0[BATCH*SS], g_r1[BATCH*SS], g_r2[BATCH*SS];
__device__ __nv_bfloat16 g_a0[BATCH*SS], g_a1[BATCH*SS], g_a2[BATCH*SS];
__device__ float g_L[BATCH*SS];
__device__ float g_W[BATCH*SS];
__device__ unsigned g_h12[BATCH][4096];
__device__ unsigned long long g_cand[BATCH][SS];
struct Sel3 { unsigned P12, kneed, T, idxT, ncand; };
__device__ Sel3 g_s3[BATCH];

__device__ __forceinline__ unsigned fkey(float f) {
    unsigned u = __float_as_uint(f);
    return (u & 0x80000000u) ? ~u : (u | 0x80000000u);
}

__device__ __forceinline__ void split3(float v, __nv_bfloat16* p0,
                                       __nv_bfloat16* p1, __nv_bfloat16* p2) {
    __nv_bfloat16 b0 = __float2bfloat16(v);
    float r = v - __bfloat162float(b0);
    __nv_bfloat16 b1 = __float2bfloat16(r);
    float r2 = r - __bfloat162float(b1);
    *p0 = b0; *p1 = b1; *p2 = __float2bfloat16(r2);
}

__device__ __forceinline__ uint32_t s2u(const void* p) {
    uint32_t a;
    asm("{ .reg .u64 t; cvta.to.shared.u64 t, %1; cvt.u32.u64 %0, t; }" : "=r"(a) : "l"(p));
    return a;
}

// ---------------- row stats ----------------
__global__ void row_stats(const float* __restrict__ x) {
    int warp = threadIdx.x >> 5, lane = threadIdx.x & 31;
    int row = blockIdx.x * 8 + warp;
    const float* xr = x + (size_t)row * CDIM;
    float v0 = xr[lane], v1 = xr[lane + 32];
    float s = v0 + v1;
    #pragma unroll
    for (int o = 16; o; o >>= 1) s += __shfl_xor_sync(0xFFFFFFFFu, s, o);
    float mean = s * (1.0f / CDIM);
    float d0 = v0 - mean, d1 = v1 - mean;
    float ss = d0 * d0 + d1 * d1;
    #pragma unroll
    for (int o = 16; o; o >>= 1) ss += __shfl_xor_sync(0xFFFFFFFFu, ss, o);
    if (lane == 0) { g_mean[row] = mean; g_std[row] = sqrtf(ss); }
}

// ---------------- fused pairwise -> bf16 splits ----------------
__global__ __launch_bounds__(256) void pairwise(const float* __restrict__ x) {
    __shared__ float xi[32][CDIM + 1];
    __shared__ float xj[32][CDIM + 1];
    __shared__ float smi[32], ssi[32], smj[32], ssj[32];
    int b = blockIdx.z;
    int i0 = blockIdx.y * 32, j0 = blockIdx.x * 32;
    const float* xb = x + (size_t)b * NTOK * CDIM;
    int tid = threadIdx.x;
    for (int l = tid; l < 32 * CDIM; l += 256) {
        int r = l >> 6, c = l & 63;
        xi[r][c] = xb[(size_t)(i0 + r) * CDIM + c];
        xj[r][c] = xb[(size_t)(j0 + r) * CDIM + c];
    }
    if (tid < 32)      { smi[tid] = g_mean[b*NTOK + i0 + tid]; ssi[tid] = g_std[b*NTOK + i0 + tid]; }
    else if (tid < 64) { int t = tid - 32; smj[t] = g_mean[b*NTOK + j0 + t]; ssj[t] = g_std[b*NTOK + j0 + t]; }
    __syncthreads();

    int tx = tid & 15, ty = tid >> 4;
    int r0 = ty * 2, r1 = ty * 2 + 1;
    int c0 = tx, c1 = tx + 16;

    float ssq[2][2] = {{0,0},{0,0}};
    float mx[2][2]  = {{0,0},{0,0}};
    float dt[2][2]  = {{0,0},{0,0}};
    float mi0 = smi[r0], mi1 = smi[r1], mj0 = smj[c0], mj1 = smj[c1];

    #pragma unroll 16
    for (int c = 0; c < CDIM; c++) {
        float a0 = xi[r0][c], a1 = xi[r1][c];
        float b0 = xj[c0][c], b1 = xj[c1][c];
        float ac0 = a0 - mi0, ac1 = a1 - mi1;
        float bc0 = b0 - mj0, bc1 = b1 - mj1;
        float d;
        d = a0 - b0; ssq[0][0] = fmaf(d,d,ssq[0][0]); mx[0][0] = fmaxf(mx[0][0], fabsf(d)); dt[0][0] = fmaf(ac0,bc0,dt[0][0]);
        d = a0 - b1; ssq[0][1] = fmaf(d,d,ssq[0][1]); mx[0][1] = fmaxf(mx[0][1], fabsf(d)); dt[0][1] = fmaf(ac0,bc1,dt[0][1]);
        d = a1 - b0; ssq[1][0] = fmaf(d,d,ssq[1][0]); mx[1][0] = fmaxf(mx[1][0], fabsf(d)); dt[1][0] = fmaf(ac1,bc0,dt[1][0]);
        d = a1 - b1; ssq[1][1] = fmaf(d,d,ssq[1][1]); mx[1][1] = fmaxf(mx[1][1], fabsf(d)); dt[1][1] = fmaf(ac1,bc1,dt[1][1]);
    }
    #pragma unroll
    for (int p = 0; p < 2; p++) {
        int I = i0 + r0 + p;
        float si = ssi[r0 + p];
        #pragma unroll
        for (int q = 0; q < 2; q++) {
            int J = j0 + ((q == 0) ? c0 : c1);
            size_t o = (size_t)b * SS + (size_t)I * NTOK + J;
            split3(sqrtf(ssq[p][q]), g_e0 + o, g_e1 + o, g_e2 + o);
            split3(mx[p][q],         g_h0 + o, g_h1 + o, g_h2 + o);
            float cr = dt[p][q] / (si * ssj[(q==0)?c0:c1]);
            cr = fminf(fmaxf(cr, -1.0f), 1.0f);
            split3(cr, g_r0 + o, g_r1 + o, g_r2 + o);
        }
    }
}

// ---------------- bf16x6 GEMM via mma.sync (HMMA): D = A * B^T ----------------
#define KC 32
#define ROWB 80
#define TILEB (128*ROWB)
#define STAGEB (6*TILEB)
#define GSMEM (2*STAGEB)

#define LDSM4(r, a) \
    asm volatile("ldmatrix.sync.aligned.m8n8.x4.shared.b16 {%0,%1,%2,%3}, [%4];" \
        : "=r"((r)[0]), "=r"((r)[1]), "=r"((r)[2]), "=r"((r)[3]) : "r"(a))

#define MMA16816(d, a, b0r, b1r) \
    asm volatile("mma.sync.aligned.m16n8k16.row.col.f32.bf16.bf16.f32 " \
        "{%0,%1,%2,%3}, {%4,%5,%6,%7}, {%8,%9}, {%0,%1,%2,%3};" \
        : "+f"((d)[0]), "+f"((d)[1]), "+f"((d)[2]), "+f"((d)[3]) \
        : "r"((a)[0]), "r"((a)[1]), "r"((a)[2]), "r"((a)[3]), "r"(b0r), "r"(b1r))

__global__ __launch_bounds__(256, 1) void gemm_mma(int which) {
    extern __shared__ __align__(128) char dsm[];
    uint32_t sb = s2u(dsm);
    int tid = threadIdx.x, lane = tid & 31, wid = tid >> 5;
    int wm = wid >> 2, wn = wid & 3;   // warp tile 64x32, grid 2x4
    size_t boff = (size_t)blockIdx.z * SS;
    const __nv_bfloat16* mats[6];
    if (which == 0) {
        mats[0]=g_e0+boff; mats[1]=g_e1+boff; mats[2]=g_e2+boff;
        mats[3]=g_h0+boff; mats[4]=g_h1+boff; mats[5]=g_h2+boff;
    } else {
        mats[0]=g_a0+boff; mats[1]=g_a1+boff; mats[2]=g_a2+boff;
        mats[3]=g_r0+boff; mats[4]=g_r1+boff; mats[5]=g_r2+boff;
    }
    float* C = (which == 0 ? g_L : g_W) + boff;
    int rowBase = blockIdx.y * 128, colBase = blockIdx.x * 128;

    float acc[4][4][4];
    #pragma unroll
    for (int i = 0; i < 4; i++)
        #pragma unroll
        for (int j = 0; j < 4; j++)
            #pragma unroll
            for (int k = 0; k < 4; k++) acc[i][j][k] = 0.0f;

    unsigned aRowOff = (unsigned)(wm*64 + (lane & 15)) * ROWB + ((lane >> 4) << 4);
    unsigned bRowOff = (unsigned)(wn*32 + (lane & 7) + ((lane >> 4) << 3)) * ROWB
                     + (((lane >> 3) & 1) << 4);

#define LOADSTAGE(st, k0) do { \
    unsigned _so = sb + (unsigned)(st)*STAGEB; \
    _Pragma("unroll") \
    for (int i = 0; i < 12; i++) { \
        int g = i * 256 + tid; \
        int mat = g >> 9, idx = g & 511; \
        int row = idx >> 2, c8 = idx & 3; \
        int rb = (mat < 3) ? rowBase : colBase; \
        const __nv_bfloat16* gp = mats[mat] + (size_t)(rb + row) * NTOK + (k0) + c8*8; \
        unsigned sa = _so + mat*TILEB + row*ROWB + c8*16; \
        asm volatile("cp.async.cg.shared.global [%0], [%1], 16;" :: "r"(sa), "l"(gp)); \
    } \
    asm volatile("cp.async.commit_group;"); \
} while(0)

    LOADSTAGE(0, 0);

    const int pa[6] = {0,0,1,0,1,2}, pb[6] = {0,1,0,2,1,0};

    for (int t = 0; t < 32; t++) {
        if (t < 31) {
            LOADSTAGE((t + 1) & 1, (t + 1) * KC);
            asm volatile("cp.async.wait_group 1;");
        } else {
            asm volatile("cp.async.wait_group 0;");
        }
        __syncthreads();
        unsigned stoff = sb + (unsigned)(t & 1) * STAGEB;
        #pragma unroll
        for (int p = 0; p < 6; p++) {
            unsigned abase = stoff + pa[p] * TILEB + aRowOff;
            unsigned bbase = stoff + (3 + pb[p]) * TILEB + bRowOff;
            #pragma unroll
            for (int kf = 0; kf < 2; kf++) {
                uint32_t af[4][4];
                #pragma unroll
                for (int mf = 0; mf < 4; mf++)
                    LDSM4(af[mf], abase + mf * (16 * ROWB) + kf * 32);
                uint32_t bf[4][4];
                #pragma unroll
                for (int np = 0; np < 2; np++)
                    LDSM4(bf[np], bbase + np * (16 * ROWB) + kf * 32);
                #pragma unroll
                for (int mf = 0; mf < 4; mf++) {
                    MMA16816(acc[mf][0], af[mf], bf[0][0], bf[0][1]);
                    MMA16816(acc[mf][1], af[mf], bf[0][2], bf[0][3]);
                    MMA16816(acc[mf][2], af[mf], bf[1][0], bf[1][1]);
                    MMA16816(acc[mf][3], af[mf], bf[1][2], bf[1][3]);
                }
            }
        }
        __syncthreads();
    }

    int r0 = rowBase + wm * 64 + (lane >> 2);
    int c0 = colBase + wn * 32 + (lane & 3) * 2;
    #pragma unroll
    for (int mf = 0; mf < 4; mf++) {
        #pragma unroll
        for (int nb = 0; nb < 4; nb++) {
            float* base = C + (size_t)(r0 + mf * 16) * NTOK + c0 + nb * 8;
            *(float2*)base = make_float2(acc[mf][nb][0], acc[mf][nb][1]);
            *(float2*)(base + 8 * NTOK) = make_float2(acc[mf][nb][2], acc[mf][nb][3]);
        }
    }
#undef LOADSTAGE
}

// ---------------- row softmax of 0.125*L -> attn bf16 splits ----------------
__global__ void softmax_rows() {
    int b = blockIdx.y, row = blockIdx.x;
    size_t base = (size_t)b * SS + (size_t)row * NTOK;
    float* L = g_L + base;
    int tid = threadIdx.x;  // 256
    float v[4];
    #pragma unroll
    for (int i = 0; i < 4; i++) v[i] = L[tid + i * 256] * 0.125f;
    float m = fmaxf(fmaxf(v[0], v[1]), fmaxf(v[2], v[3]));
    __shared__ float red[256];
    red[tid] = m; __syncthreads();
    for (int s = 128; s; s >>= 1) { if (tid < s) red[tid] = fmaxf(red[tid], red[tid + s]); __syncthreads(); }
    m = red[0]; __syncthreads();
    float e[4], sm = 0.0f;
    #pragma unroll
    for (int i = 0; i < 4; i++) { e[i] = expf(v[i] - m); sm += e[i]; }
    red[tid] = sm; __syncthreads();
    for (int s = 128; s; s >>= 1) { if (tid < s) red[tid] += red[tid + s]; __syncthreads(); }
    sm = red[0];
    #pragma unroll
    for (int i = 0; i < 4; i++) {
        size_t o = base + tid + i * 256;
        split3(e[i] / sm, g_a0 + o, g_a1 + o, g_a2 + o);
    }
}

// ---------------- top-k selection: 12-bit hist + gather + single-block finish ----------------
__global__ void sel_zero() {
    int i = blockIdx.x * 1024 + threadIdx.x;   // BATCH*4096 = 8192 -> 8 blocks
    ((unsigned*)g_h12)[i] = 0;
    if (i < BATCH) g_s3[i].ncand = 0;
}

__global__ void sel_hist12() {
    int b = blockIdx.y;
    __shared__ unsigned h[4096];
    for (int i = threadIdx.x; i < 4096; i += blockDim.x) h[i] = 0;
    __syncthreads();
    const float4* W = (const float4*)(g_W + (size_t)b * SS);
    for (int i = blockIdx.x * blockDim.x + threadIdx.x; i < SS/4; i += gridDim.x * blockDim.x) {
        float4 v = W[i];
        atomicAdd(&h[fkey(v.x) >> 20], 1u);
        atomicAdd(&h[fkey(v.y) >> 20], 1u);
        atomicAdd(&h[fkey(v.z) >> 20], 1u);
        atomicAdd(&h[fkey(v.w) >> 20], 1u);
    }
    __syncthreads();
    for (int i = threadIdx.x; i < 4096; i += blockDim.x)
        if (h[i]) atomicAdd(&g_h12[b][i], h[i]);
}

__global__ void sel_scan12() {   // 1 block of 256 per batch
    int b = blockIdx.x, tid = threadIdx.x;
    __shared__ unsigned csum[256];
    unsigned s = 0;
    for (int k = 0; k < 16; k++) s += g_h12[b][tid * 16 + k];
    csum[tid] = s;
    __syncthreads();
    if (tid == 0) {
        unsigned acc = 0; int c = 255;
        for (; c >= 0; c--) { if (acc + csum[c] >= (unsigned)KSEL) break; acc += csum[c]; }
        int bin = c * 16 + 15;
        for (;; bin--) { unsigned ct = g_h12[b][bin]; if (acc + ct >= (unsigned)KSEL) break; acc += ct; }
        g_s3[b].P12 = (unsigned)bin;
        g_s3[b].kneed = (unsigned)KSEL - acc;
    }
}

__global__ void sel_gather12() {
    int b = blockIdx.y;
    unsigned P = g_s3[b].P12;
    const float4* W = (const float4*)(g_W + (size_t)b * SS);
    for (int i = blockIdx.x * blockDim.x + threadIdx.x; i < SS/4; i += gridDim.x * blockDim.x) {
        float4 v = W[i];
        unsigned base = i * 4;
        float vv[4] = {v.x, v.y, v.z, v.w};
        #pragma unroll
        for (int j = 0; j < 4; j++) {
            unsigned u = fkey(vv[j]);
            if ((u >> 20) == P) {
                unsigned pos = atomicAdd(&g_s3[b].ncand, 1u);
                g_cand[b][pos] = ((unsigned long long)u << 32) | (base + j);
            }
        }
    }
}

__global__ void sel_finish() {  // 1 block of 1024 per batch
    int b = blockIdx.x, tid = threadIdx.x;
    __shared__ unsigned h[256];
    __shared__ unsigned s_prefix, s_kneed;
    unsigned n = g_s3[b].ncand;
    if (tid == 0) { s_prefix = 0; s_kneed = g_s3[b].kneed; }
    __syncthreads();
    const int shs[3] = {12, 4, 0};
    const unsigned wids[3] = {256, 256, 16};
    // select kneed-th largest low-20 key bits among candidates
    #pragma unroll
    for (int lvl = 0; lvl < 3; lvl++) {
        int sh = shs[lvl];
        unsigned w = wids[lvl];
        unsigned pmask = (lvl == 0) ? 0u : (0xFFFFFu << (shs[lvl-1]));
        if (tid < w) h[tid] = 0;
        __syncthreads();
        unsigned pfx = s_prefix;
        for (unsigned i = tid; i < n; i += 1024) {
            unsigned low = ((unsigned)(g_cand[b][i] >> 32)) & 0xFFFFFu;
            if ((low & pmask) == pfx) atomicAdd(&h[(low >> sh) & (w - 1)], 1u);
        }
        __syncthreads();
        if (tid == 0) {
            unsigned kneed = s_kneed;
            int bin = (int)w - 1;
            for (; bin >= 0; bin--) { if (kneed <= h[bin]) break; kneed -= h[bin]; }
            s_prefix = pfx | ((unsigned)bin << sh);
            s_kneed = kneed;
        }
        __syncthreads();
    }
    unsigned T = (g_s3[b].P12 << 20) | s_prefix;
    // tie-break: select kneed-th largest idx among exact-T candidates (idx < 2^20)
    if (tid == 0) s_prefix = 0;
    __syncthreads();
    #pragma unroll
    for (int lvl = 0; lvl < 3; lvl++) {
        int sh = shs[lvl];
        unsigned w = wids[lvl];
        unsigned pmask = (lvl == 0) ? 0u : (0xFFFFFu << (shs[lvl-1]));
        if (tid < w) h[tid] = 0;
        __syncthreads();
        unsigned pfx = s_prefix;
        for (unsigned i = tid; i < n; i += 1024) {
            unsigned long long cv = g_cand[b][i];
            unsigned key = (unsigned)(cv >> 32);
            unsigned idx = (unsigned)cv;
            if (key == T && (idx & pmask) == pfx) atomicAdd(&h[(idx >> sh) & (w - 1)], 1u);
        }
        __syncthreads();
        if (tid == 0) {
            unsigned kneed = s_kneed;
            int bin = (int)w - 1;
            for (; bin >= 0; bin--) { if (kneed <= h[bin]) break; kneed -= h[bin]; }
            s_prefix = pfx | ((unsigned)bin << sh);
            s_kneed = kneed;
        }
        __syncthreads();
    }
    if (tid == 0) { g_s3[b].T = T; g_s3[b].idxT = s_prefix; }
}

__global__ void mask_write(float* __restrict__ out) {
    int b = blockIdx.y;
    unsigned base = (blockIdx.x * 1024 + threadIdx.x) * 4;
    unsigned T = g_s3[b].T;
    unsigned idxT = g_s3[b].idxT;
    const float4 v = *(const float4*)(g_W + (size_t)b * SS + base);
    float r[4]; const float vv[4] = {v.x, v.y, v.z, v.w};
    #pragma unroll
    for (int j = 0; j < 4; j++) {
        unsigned u = fkey(vv[j]);
        r[j] = (u > T || (u == T && base + j >= idxT)) ? 1.0f : 0.0f;
    }
    *(float4*)(out + (size_t)b * SS + base) = make_float4(r[0], r[1], r[2], r[3]);
}

// ---------------- launcher ----------------
extern "C" void kernel_launch(void* const* d_in, const int* in_sizes, int n_in,
                              void* d_out, int out_size) {
    const float* x = (const float*)d_in[0];
    float* out = (float*)d_out;

    cudaFuncSetAttribute(gemm_mma, cudaFuncAttributeMaxDynamicSharedMemorySize, GSMEM);

    row_stats<<<(BATCH * NTOK) / 8, 256>>>(x);
    pairwise<<<dim3(32, 32, BATCH), 256>>>(x);
    gemm_mma<<<dim3(8, 8, BATCH), 256, GSMEM>>>(0);
    softmax_rows<<<dim3(NTOK, BATCH), 256>>>();
    gemm_mma<<<dim3(8, 8, BATCH), 256, GSMEM>>>(1);

    sel_zero<<<(BATCH * 4096) / 1024, 1024>>>();
    sel_hist12<<<dim3(128, BATCH), 256>>>();
    sel_scan12<<<BATCH, 256>>>();
    sel_gather12<<<dim3(128, BATCH), 256>>>();
    sel_finish<<<BATCH, 1024>>>();
    mask_write<<<dim3(SS / 4096, BATCH), 1024>>>(out);
}

// round 9
// speedup vs baseline: 1.4505x; 1.0306x over previous
#include <cuda_runtime.h>
#include <cuda_bf16.h>
#include <math.h>
#include <stdint.h>

#define NTOK 1024
#define CDIM 64
#define BATCH 2
#define SS (NTOK*NTOK)
#define KSEL (SS/6)   /* 174762 */

// ---------------- device scratch (no allocations allowed) ----------------
__device__ float g_mean[BATCH*NTOK];
__device__ float g_std[BATCH*NTOK];
__device__ __nv_bfloat16 g_e0[BATCH*SS], g_e1[BATCH*SS], g_e2[BATCH*SS];
__device__ __nv_bfloat16 g_h0[BATCH*SS], g_h1[BATCH*SS], g_h2[BATCH*SS];
__device__ __nv_bfloat16 g_r0[BATCH*SS], g_r1[BATCH*SS], g_r2[BATCH*SS];
__device__ __nv_bfloat16 g_a0[BATCH*SS], g_a1[BATCH*SS], g_a2[BATCH*SS];
__device__ float g_L[BATCH*SS];
__device__ float g_W[BATCH*SS];
__device__ unsigned g_h12[BATCH][4096];
__device__ unsigned long long g_cand[BATCH][SS];
struct Sel3 { unsigned P12, kneed, T, idxT, ncand; };
__device__ Sel3 g_s3[BATCH];

__device__ __forceinline__ unsigned fkey(float f) {
    unsigned u = __float_as_uint(f);
    return (u & 0x80000000u) ? ~u : (u | 0x80000000u);
}

__device__ __forceinline__ void split3(float v, __nv_bfloat16* p0,
                                       __nv_bfloat16* p1, __nv_bfloat16* p2) {
    __nv_bfloat16 b0 = __float2bfloat16(v);
    float r = v - __bfloat162float(b0);
    __nv_bfloat16 b1 = __float2bfloat16(r);
    float r2 = r - __bfloat162float(b1);
    *p0 = b0; *p1 = b1; *p2 = __float2bfloat16(r2);
}

__device__ __forceinline__ uint32_t s2u(const void* p) {
    uint32_t a;
    asm("{ .reg .u64 t; cvta.to.shared.u64 t, %1; cvt.u32.u64 %0, t; }" : "=r"(a) : "l"(p));
    return a;
}

// ---------------- row stats (+ zero selection state for this replay) ----------------
__global__ void row_stats(const float* __restrict__ x) {
    int gid = blockIdx.x * blockDim.x + threadIdx.x;
    if (gid < BATCH * 4096) ((unsigned*)g_h12)[gid] = 0;
    if (gid < BATCH) g_s3[gid].ncand = 0;

    int warp = threadIdx.x >> 5, lane = threadIdx.x & 31;
    int row = blockIdx.x * 8 + warp;
    const float* xr = x + (size_t)row * CDIM;
    float v0 = xr[lane], v1 = xr[lane + 32];
    float s = v0 + v1;
    #pragma unroll
    for (int o = 16; o; o >>= 1) s += __shfl_xor_sync(0xFFFFFFFFu, s, o);
    float mean = s * (1.0f / CDIM);
    float d0 = v0 - mean, d1 = v1 - mean;
    float ss = d0 * d0 + d1 * d1;
    #pragma unroll
    for (int o = 16; o; o >>= 1) ss += __shfl_xor_sync(0xFFFFFFFFu, ss, o);
    if (lane == 0) { g_mean[row] = mean; g_std[row] = sqrtf(ss); }
}

// ---------------- fused pairwise -> bf16 splits ----------------
__global__ __launch_bounds__(256) void pairwise(const float* __restrict__ x) {
    __shared__ float xi[32][CDIM + 1];
    __shared__ float xj[32][CDIM + 1];
    __shared__ float smi[32], ssi[32], smj[32], ssj[32];
    int b = blockIdx.z;
    int i0 = blockIdx.y * 32, j0 = blockIdx.x * 32;
    const float* xb = x + (size_t)b * NTOK * CDIM;
    int tid = threadIdx.x;
    for (int l = tid; l < 32 * CDIM; l += 256) {
        int r = l >> 6, c = l & 63;
        xi[r][c] = xb[(size_t)(i0 + r) * CDIM + c];
        xj[r][c] = xb[(size_t)(j0 + r) * CDIM + c];
    }
    if (tid < 32)      { smi[tid] = g_mean[b*NTOK + i0 + tid]; ssi[tid] = g_std[b*NTOK + i0 + tid]; }
    else if (tid < 64) { int t = tid - 32; smj[t] = g_mean[b*NTOK + j0 + t]; ssj[t] = g_std[b*NTOK + j0 + t]; }
    __syncthreads();

    int tx = tid & 15, ty = tid >> 4;
    int r0 = ty * 2, r1 = ty * 2 + 1;
    int c0 = tx, c1 = tx + 16;

    float ssq[2][2] = {{0,0},{0,0}};
    float mx[2][2]  = {{0,0},{0,0}};
    float dt[2][2]  = {{0,0},{0,0}};
    float mi0 = smi[r0], mi1 = smi[r1], mj0 = smj[c0], mj1 = smj[c1];

    #pragma unroll 16
    for (int c = 0; c < CDIM; c++) {
        float a0 = xi[r0][c], a1 = xi[r1][c];
        float b0 = xj[c0][c], b1 = xj[c1][c];
        float ac0 = a0 - mi0, ac1 = a1 - mi1;
        float bc0 = b0 - mj0, bc1 = b1 - mj1;
        float d;
        d = a0 - b0; ssq[0][0] = fmaf(d,d,ssq[0][0]); mx[0][0] = fmaxf(mx[0][0], fabsf(d)); dt[0][0] = fmaf(ac0,bc0,dt[0][0]);
        d = a0 - b1; ssq[0][1] = fmaf(d,d,ssq[0][1]); mx[0][1] = fmaxf(mx[0][1], fabsf(d)); dt[0][1] = fmaf(ac0,bc1,dt[0][1]);
        d = a1 - b0; ssq[1][0] = fmaf(d,d,ssq[1][0]); mx[1][0] = fmaxf(mx[1][0], fabsf(d)); dt[1][0] = fmaf(ac1,bc0,dt[1][0]);
        d = a1 - b1; ssq[1][1] = fmaf(d,d,ssq[1][1]); mx[1][1] = fmaxf(mx[1][1], fabsf(d)); dt[1][1] = fmaf(ac1,bc1,dt[1][1]);
    }
    #pragma unroll
    for (int p = 0; p < 2; p++) {
        int I = i0 + r0 + p;
        float si = ssi[r0 + p];
        #pragma unroll
        for (int q = 0; q < 2; q++) {
            int J = j0 + ((q == 0) ? c0 : c1);
            size_t o = (size_t)b * SS + (size_t)I * NTOK + J;
            split3(sqrtf(ssq[p][q]), g_e0 + o, g_e1 + o, g_e2 + o);
            split3(mx[p][q],         g_h0 + o, g_h1 + o, g_h2 + o);
            float cr = dt[p][q] / (si * ssj[(q==0)?c0:c1]);
            cr = fminf(fmaxf(cr, -1.0f), 1.0f);
            split3(cr, g_r0 + o, g_r1 + o, g_r2 + o);
        }
    }
}

// ---------------- bf16x6 GEMM via mma.sync (HMMA): D = A * B^T ----------------
#define KC 32
#define ROWB 80
#define TILEB (128*ROWB)
#define STAGEB (6*TILEB)
#define GSMEM (2*STAGEB)

#define LDSM4(r, a) \
    asm volatile("ldmatrix.sync.aligned.m8n8.x4.shared.b16 {%0,%1,%2,%3}, [%4];" \
        : "=r"((r)[0]), "=r"((r)[1]), "=r"((r)[2]), "=r"((r)[3]) : "r"(a))

#define MMA16816(d, a, b0r, b1r) \
    asm volatile("mma.sync.aligned.m16n8k16.row.col.f32.bf16.bf16.f32 " \
        "{%0,%1,%2,%3}, {%4,%5,%6,%7}, {%8,%9}, {%0,%1,%2,%3};" \
        : "+f"((d)[0]), "+f"((d)[1]), "+f"((d)[2]), "+f"((d)[3]) \
        : "r"((a)[0]), "r"((a)[1]), "r"((a)[2]), "r"((a)[3]), "r"(b0r), "r"(b1r))

__global__ __launch_bounds__(256, 1) void gemm_mma(int which) {
    extern __shared__ __align__(128) char dsm[];
    uint32_t sb = s2u(dsm);
    int tid = threadIdx.x, lane = tid & 31, wid = tid >> 5;
    int wm = wid >> 2, wn = wid & 3;   // warp tile 64x32, grid 2x4
    size_t boff = (size_t)blockIdx.z * SS;
    const __nv_bfloat16* mats[6];
    if (which == 0) {
        mats[0]=g_e0+boff; mats[1]=g_e1+boff; mats[2]=g_e2+boff;
        mats[3]=g_h0+boff; mats[4]=g_h1+boff; mats[5]=g_h2+boff;
    } else {
        mats[0]=g_a0+boff; mats[1]=g_a1+boff; mats[2]=g_a2+boff;
        mats[3]=g_r0+boff; mats[4]=g_r1+boff; mats[5]=g_r2+boff;
    }
    float* C = (which == 0 ? g_L : g_W) + boff;
    int rowBase = blockIdx.y * 128, colBase = blockIdx.x * 128;

    float acc[4][4][4];
    #pragma unroll
    for (int i = 0; i < 4; i++)
        #pragma unroll
        for (int j = 0; j < 4; j++)
            #pragma unroll
            for (int k = 0; k < 4; k++) acc[i][j][k] = 0.0f;

    unsigned aRowOff = (unsigned)(wm*64 + (lane & 15)) * ROWB + ((lane >> 4) << 4);
    unsigned bRowOff = (unsigned)(wn*32 + (lane & 7) + ((lane >> 4) << 3)) * ROWB
                     + (((lane >> 3) & 1) << 4);

#define LOADSTAGE(st, k0) do { \
    unsigned _so = sb + (unsigned)(st)*STAGEB; \
    _Pragma("unroll") \
    for (int i = 0; i < 12; i++) { \
        int g = i * 256 + tid; \
        int mat = g >> 9, idx = g & 511; \
        int row = idx >> 2, c8 = idx & 3; \
        int rb = (mat < 3) ? rowBase : colBase; \
        const __nv_bfloat16* gp = mats[mat] + (size_t)(rb + row) * NTOK + (k0) + c8*8; \
        unsigned sa = _so + mat*TILEB + row*ROWB + c8*16; \
        asm volatile("cp.async.cg.shared.global [%0], [%1], 16;" :: "r"(sa), "l"(gp)); \
    } \
    asm volatile("cp.async.commit_group;"); \
} while(0)

    LOADSTAGE(0, 0);

    const int pa[6] = {0,0,1,0,1,2}, pb[6] = {0,1,0,2,1,0};

    for (int t = 0; t < 32; t++) {
        if (t < 31) {
            LOADSTAGE((t + 1) & 1, (t + 1) * KC);
            asm volatile("cp.async.wait_group 1;");
        } else {
            asm volatile("cp.async.wait_group 0;");
        }
        __syncthreads();
        unsigned stoff = sb + (unsigned)(t & 1) * STAGEB;
        #pragma unroll
        for (int kf = 0; kf < 2; kf++) {
            // fragment reuse: load each split's fragments ONCE per kf
            uint32_t af[3][4][4];
            uint32_t bf[3][2][4];
            #pragma unroll
            for (int s = 0; s < 3; s++) {
                #pragma unroll
                for (int mf = 0; mf < 4; mf++)
                    LDSM4(af[s][mf], stoff + s*TILEB + aRowOff + mf*(16*ROWB) + kf*32);
                #pragma unroll
                for (int np = 0; np < 2; np++)
                    LDSM4(bf[s][np], stoff + (3+s)*TILEB + bRowOff + np*(16*ROWB) + kf*32);
            }
            #pragma unroll
            for (int p = 0; p < 6; p++) {
                int sa = pa[p], sbp = pb[p];
                #pragma unroll
                for (int mf = 0; mf < 4; mf++) {
                    MMA16816(acc[mf][0], af[sa][mf], bf[sbp][0][0], bf[sbp][0][1]);
                    MMA16816(acc[mf][1], af[sa][mf], bf[sbp][0][2], bf[sbp][0][3]);
                    MMA16816(acc[mf][2], af[sa][mf], bf[sbp][1][0], bf[sbp][1][1]);
                    MMA16816(acc[mf][3], af[sa][mf], bf[sbp][1][2], bf[sbp][1][3]);
                }
            }
        }
        __syncthreads();
    }

    int r0 = rowBase + wm * 64 + (lane >> 2);
    int c0 = colBase + wn * 32 + (lane & 3) * 2;
    #pragma unroll
    for (int mf = 0; mf < 4; mf++) {
        #pragma unroll
        for (int nb = 0; nb < 4; nb++) {
            float* base = C + (size_t)(r0 + mf * 16) * NTOK + c0 + nb * 8;
            *(float2*)base = make_float2(acc[mf][nb][0], acc[mf][nb][1]);
            *(float2*)(base + 8 * NTOK) = make_float2(acc[mf][nb][2], acc[mf][nb][3]);
        }
    }

    // ---- fused selection histogram (gemm2 only): W values are in registers ----
    if (which == 1) {
        unsigned* hist = (unsigned*)dsm;
        __syncthreads();  // done with smem tiles
        for (int i = tid; i < 4096; i += 256) hist[i] = 0;
        __syncthreads();
        #pragma unroll
        for (int mf = 0; mf < 4; mf++)
            #pragma unroll
            for (int nb = 0; nb < 4; nb++)
                #pragma unroll
                for (int k = 0; k < 4; k++)
                    atomicAdd(&hist[fkey(acc[mf][nb][k]) >> 20], 1u);
        __syncthreads();
        int b = blockIdx.z;
        for (int i = tid; i < 4096; i += 256)
            if (hist[i]) atomicAdd(&g_h12[b][i], hist[i]);
    }
#undef LOADSTAGE
}

// ---------------- row softmax of 0.125*L -> attn bf16 splits ----------------
__global__ void softmax_rows() {
    int b = blockIdx.y, row = blockIdx.x;
    size_t base = (size_t)b * SS + (size_t)row * NTOK;
    float* L = g_L + base;
    int tid = threadIdx.x;  // 256
    float v[4];
    #pragma unroll
    for (int i = 0; i < 4; i++) v[i] = L[tid + i * 256] * 0.125f;
    float m = fmaxf(fmaxf(v[0], v[1]), fmaxf(v[2], v[3]));
    __shared__ float red[256];
    red[tid] = m; __syncthreads();
    for (int s = 128; s; s >>= 1) { if (tid < s) red[tid] = fmaxf(red[tid], red[tid + s]); __syncthreads(); }
    m = red[0]; __syncthreads();
    float e[4], sm = 0.0f;
    #pragma unroll
    for (int i = 0; i < 4; i++) { e[i] = expf(v[i] - m); sm += e[i]; }
    red[tid] = sm; __syncthreads();
    for (int s = 128; s; s >>= 1) { if (tid < s) red[tid] += red[tid + s]; __syncthreads(); }
    sm = red[0];
    #pragma unroll
    for (int i = 0; i < 4; i++) {
        size_t o = base + tid + i * 256;
        split3(e[i] / sm, g_a0 + o, g_a1 + o, g_a2 + o);
    }
}

// ---------------- top-k selection ----------------
__global__ void sel_scan12() {   // 1 block of 256 per batch
    int b = blockIdx.x, tid = threadIdx.x;
    __shared__ unsigned csum[256];
    unsigned s = 0;
    for (int k = 0; k < 16; k++) s += g_h12[b][tid * 16 + k];
    csum[tid] = s;
    __syncthreads();
    if (tid == 0) {
        unsigned acc = 0; int c = 255;
        for (; c >= 0; c--) { if (acc + csum[c] >= (unsigned)KSEL) break; acc += csum[c]; }
        int bin = c * 16 + 15;
        for (;; bin--) { unsigned ct = g_h12[b][bin]; if (acc + ct >= (unsigned)KSEL) break; acc += ct; }
        g_s3[b].P12 = (unsigned)bin;
        g_s3[b].kneed = (unsigned)KSEL - acc;
    }
}

__global__ void sel_gather12() {
    int b = blockIdx.y;
    unsigned P = g_s3[b].P12;
    const float4* W = (const float4*)(g_W + (size_t)b * SS);
    for (int i = blockIdx.x * blockDim.x + threadIdx.x; i < SS/4; i += gridDim.x * blockDim.x) {
        float4 v = W[i];
        unsigned base = i * 4;
        float vv[4] = {v.x, v.y, v.z, v.w};
        #pragma unroll
        for (int j = 0; j < 4; j++) {
            unsigned u = fkey(vv[j]);
            if ((u >> 20) == P) {
                unsigned pos = atomicAdd(&g_s3[b].ncand, 1u);
                g_cand[b][pos] = ((unsigned long long)u << 32) | (base + j);
            }
        }
    }
}

__global__ void sel_finish() {  // 1 block of 1024 per batch
    int b = blockIdx.x, tid = threadIdx.x;
    __shared__ unsigned h[256];
    __shared__ unsigned s_prefix, s_kneed;
    unsigned n = g_s3[b].ncand;
    if (tid == 0) { s_prefix = 0; s_kneed = g_s3[b].kneed; }
    __syncthreads();
    const int shs[3] = {12, 4, 0};
    const unsigned wids[3] = {256, 256, 16};
    #pragma unroll
    for (int lvl = 0; lvl < 3; lvl++) {
        int sh = shs[lvl];
        unsigned w = wids[lvl];
        unsigned pmask = (lvl == 0) ? 0u : (0xFFFFFu << (shs[lvl-1]));
        if (tid < w) h[tid] = 0;
        __syncthreads();
        unsigned pfx = s_prefix;
        for (unsigned i = tid; i < n; i += 1024) {
            unsigned low = ((unsigned)(g_cand[b][i] >> 32)) & 0xFFFFFu;
            if ((low & pmask) == pfx) atomicAdd(&h[(low >> sh) & (w - 1)], 1u);
        }
        __syncthreads();
        if (tid == 0) {
            unsigned kneed = s_kneed;
            int bin = (int)w - 1;
            for (; bin >= 0; bin--) { if (kneed <= h[bin]) break; kneed -= h[bin]; }
            s_prefix = pfx | ((unsigned)bin << sh);
            s_kneed = kneed;
        }
        __syncthreads();
    }
    unsigned T = (g_s3[b].P12 << 20) | s_prefix;
    if (tid == 0) s_prefix = 0;
    __syncthreads();
    #pragma unroll
    for (int lvl = 0; lvl < 3; lvl++) {
        int sh = shs[lvl];
        unsigned w = wids[lvl];
        unsigned pmask = (lvl == 0) ? 0u : (0xFFFFFu << (shs[lvl-1]));
        if (tid < w) h[tid] = 0;
        __syncthreads();
        unsigned pfx = s_prefix;
        for (unsigned i = tid; i < n; i += 1024) {
            unsigned long long cv = g_cand[b][i];
            unsigned key = (unsigned)(cv >> 32);
            unsigned idx = (unsigned)cv;
            if (key == T && (idx & pmask) == pfx) atomicAdd(&h[(idx >> sh) & (w - 1)], 1u);
        }
        __syncthreads();
        if (tid == 0) {
            unsigned kneed = s_kneed;
            int bin = (int)w - 1;
            for (; bin >= 0; bin--) { if (kneed <= h[bin]) break; kneed -= h[bin]; }
            s_prefix = pfx | ((unsigned)bin << sh);
            s_kneed = kneed;
        }
        __syncthreads();
    }
    if (tid == 0) { g_s3[b].T = T; g_s3[b].idxT = s_prefix; }
}

__global__ void mask_write(float* __restrict__ out) {
    int b = blockIdx.y;
    unsigned base = (blockIdx.x * 1024 + threadIdx.x) * 4;
    unsigned T = g_s3[b].T;
    unsigned idxT = g_s3[b].idxT;
    const float4 v = *(const float4*)(g_W + (size_t)b * SS + base);
    float r[4]; const float vv[4] = {v.x, v.y, v.z, v.w};
    #pragma unroll
    for (int j = 0; j < 4; j++) {
        unsigned u = fkey(vv[j]);
        r[j] = (u > T || (u == T && base + j >= idxT)) ? 1.0f : 0.0f;
    }
    *(float4*)(out + (size_t)b * SS + base) = make_float4(r[0], r[1], r[2], r[3]);
}

// ---------------- launcher ----------------
extern "C" void kernel_launch(void* const* d_in, const int* in_sizes, int n_in,
                              void* d_out, int out_size) {
    const float* x = (const float*)d_in[0];
    float* out = (float*)d_out;

    cudaFuncSetAttribute(gemm_mma, cudaFuncAttributeMaxDynamicSharedMemorySize, GSMEM);

    row_stats<<<(BATCH * NTOK) / 8, 256>>>(x);
    pairwise<<<dim3(32, 32, BATCH), 256>>>(x);
    gemm_mma<<<dim3(8, 8, BATCH), 256, GSMEM>>>(0);
    softmax_rows<<<dim3(NTOK, BATCH), 256>>>();
    gemm_mma<<<dim3(8, 8, BATCH), 256, GSMEM>>>(1);

    sel_scan12<<<BATCH, 256>>>();
    sel_gather12<<<dim3(128, BATCH), 256>>>();
    sel_finish<<<BATCH, 1024>>>();
    mask_write<<<dim3(SS / 4096, BATCH), 1024>>>(out);
}

// round 11
// speedup vs baseline: 1.4870x; 1.0251x over previous
#include <cuda_runtime.h>
#include <cuda_bf16.h>
#include <math.h>
#include <stdint.h>

#define NTOK 1024
#define CDIM 64
#define BATCH 2
#define SS (NTOK*NTOK)
#define KSEL (SS/6)   /* 174762 */

// ---------------- device scratch (no allocations allowed) ----------------
__device__ __nv_bfloat16 g_e0[BATCH*SS], g_e1[BATCH*SS], g_e2[BATCH*SS];
__device__ __nv_bfloat16 g_h0[BATCH*SS], g_h1[BATCH*SS], g_h2[BATCH*SS];
__device__ __nv_bfloat16 g_r0[BATCH*SS], g_r1[BATCH*SS], g_r2[BATCH*SS];
__device__ __nv_bfloat16 g_a0[BATCH*SS], g_a1[BATCH*SS], g_a2[BATCH*SS];
__device__ float g_L[BATCH*SS];
__device__ float g_W[BATCH*SS];
__device__ unsigned g_h12[BATCH][4096];
__device__ unsigned long long g_cand[BATCH][SS];
struct Sel3 { unsigned P12, kneed, T, idxT, ncand; };
__device__ Sel3 g_s3[BATCH];

__device__ __forceinline__ unsigned fkey(float f) {
    unsigned u = __float_as_uint(f);
    return (u & 0x80000000u) ? ~u : (u | 0x80000000u);
}

__device__ __forceinline__ void split3(float v, __nv_bfloat16* p0,
                                       __nv_bfloat16* p1, __nv_bfloat16* p2) {
    __nv_bfloat16 b0 = __float2bfloat16(v);
    float r = v - __bfloat162float(b0);
    __nv_bfloat16 b1 = __float2bfloat16(r);
    float r2 = r - __bfloat162float(b1);
    *p0 = b0; *p1 = b1; *p2 = __float2bfloat16(r2);
}

__device__ __forceinline__ uint32_t s2u(const void* p) {
    uint32_t a;
    asm("{ .reg .u64 t; cvta.to.shared.u64 t, %1; cvt.u32.u64 %0, t; }" : "=r"(a) : "l"(p));
    return a;
}

// ---------------- fused pairwise (upper triangle) -> bf16 splits ----------------
// All three matrices are bitwise symmetric; compute (bi,bj) with bi<=bj and
// mirror the block via one smem transpose stage. Row stats computed in-block
// (bitwise identical to the old row_stats reduction).
__global__ __launch_bounds__(256) void pairwise(const float* __restrict__ x) {
    __shared__ float xi[32][CDIM + 1];
    __shared__ float xj[32][CDIM + 1];
    __shared__ float smi[32], ssi[32], smj[32], ssj[32];
    __shared__ __nv_bfloat16 tb[9][32][36];   // padded: conflict-free transpose
    int b = blockIdx.z;
    int t = blockIdx.x;
    int tid = threadIdx.x;

    // replay-safe zeroing of selection state (batch-0 blocks 0..31)
    if (b == 0 && t < 32) {
        int gid = t * 256 + tid;
        ((unsigned*)g_h12)[gid] = 0;          // BATCH*4096 = 8192
        if (gid < BATCH) g_s3[gid].ncand = 0;
    }

    // decode t -> (bi, bj), bi <= bj (32 block-rows)
    int bi = (int)((65.0f - sqrtf(4225.0f - 8.0f * (float)t)) * 0.5f);
    while (32*bi - bi*(bi-1)/2 > t) bi--;
    while (32*(bi+1) - (bi+1)*bi/2 <= t) bi++;
    int bj = bi + (t - (32*bi - bi*(bi-1)/2));
    int i0 = bi * 32, j0 = bj * 32;

    const float* xb = x + (size_t)b * NTOK * CDIM;
    for (int l = tid; l < 32 * CDIM; l += 256) {
        int r = l >> 6, c = l & 63;
        xi[r][c] = xb[(size_t)(i0 + r) * CDIM + c];
        xj[r][c] = xb[(size_t)(j0 + r) * CDIM + c];
    }
    __syncthreads();

    // per-row mean/std: 8 warps x 4 rows, identical reduction as old row_stats
    {
        int warp = tid >> 5, lane = tid & 31;
        #pragma unroll
        for (int rr = 0; rr < 4; rr++) {
            int row = warp * 4 + rr;
            {
                float v0 = xi[row][lane], v1 = xi[row][lane + 32];
                float s = v0 + v1;
                #pragma unroll
                for (int o = 16; o; o >>= 1) s += __shfl_xor_sync(0xFFFFFFFFu, s, o);
                float mean = s * (1.0f / CDIM);
                float d0 = v0 - mean, d1 = v1 - mean;
                float ss = d0 * d0 + d1 * d1;
                #pragma unroll
                for (int o = 16; o; o >>= 1) ss += __shfl_xor_sync(0xFFFFFFFFu, ss, o);
                if (lane == 0) { smi[row] = mean; ssi[row] = sqrtf(ss); }
            }
            {
                float v0 = xj[row][lane], v1 = xj[row][lane + 32];
                float s = v0 + v1;
                #pragma unroll
                for (int o = 16; o; o >>= 1) s += __shfl_xor_sync(0xFFFFFFFFu, s, o);
                float mean = s * (1.0f / CDIM);
                float d0 = v0 - mean, d1 = v1 - mean;
                float ss = d0 * d0 + d1 * d1;
                #pragma unroll
                for (int o = 16; o; o >>= 1) ss += __shfl_xor_sync(0xFFFFFFFFu, ss, o);
                if (lane == 0) { smj[row] = mean; ssj[row] = sqrtf(ss); }
            }
        }
    }
    __syncthreads();

    int tx = tid & 15, ty = tid >> 4;
    int r0 = ty * 2, r1 = ty * 2 + 1;
    int c0 = tx, c1 = tx + 16;

    float ssq[2][2] = {{0,0},{0,0}};
    float mx[2][2]  = {{0,0},{0,0}};
    float dt[2][2]  = {{0,0},{0,0}};
    float mi0 = smi[r0], mi1 = smi[r1], mj0 = smj[c0], mj1 = smj[c1];

    #pragma unroll 16
    for (int c = 0; c < CDIM; c++) {
        float a0 = xi[r0][c], a1 = xi[r1][c];
        float b0 = xj[c0][c], b1 = xj[c1][c];
        float ac0 = a0 - mi0, ac1 = a1 - mi1;
        float bc0 = b0 - mj0, bc1 = b1 - mj1;
        float d;
        d = a0 - b0; ssq[0][0] = fmaf(d,d,ssq[0][0]); mx[0][0] = fmaxf(mx[0][0], fabsf(d)); dt[0][0] = fmaf(ac0,bc0,dt[0][0]);
        d = a0 - b1; ssq[0][1] = fmaf(d,d,ssq[0][1]); mx[0][1] = fmaxf(mx[0][1], fabsf(d)); dt[0][1] = fmaf(ac0,bc1,dt[0][1]);
        d = a1 - b0; ssq[1][0] = fmaf(d,d,ssq[1][0]); mx[1][0] = fmaxf(mx[1][0], fabsf(d)); dt[1][0] = fmaf(ac1,bc0,dt[1][0]);
        d = a1 - b1; ssq[1][1] = fmaf(d,d,ssq[1][1]); mx[1][1] = fmaxf(mx[1][1], fabsf(d)); dt[1][1] = fmaf(ac1,bc1,dt[1][1]);
    }

    size_t boff = (size_t)b * SS;
    __nv_bfloat16* Gm[9] = { g_e0+boff, g_e1+boff, g_e2+boff,
                             g_h0+boff, g_h1+boff, g_h2+boff,
                             g_r0+boff, g_r1+boff, g_r2+boff };
    __nv_bfloat16 sv[9][2][2];
    #pragma unroll
    for (int p = 0; p < 2; p++) {
        float si = ssi[r0 + p];
        #pragma unroll
        for (int q = 0; q < 2; q++) {
            split3(sqrtf(ssq[p][q]), &sv[0][p][q], &sv[1][p][q], &sv[2][p][q]);
            split3(mx[p][q],         &sv[3][p][q], &sv[4][p][q], &sv[5][p][q]);
            float cr = dt[p][q] / (si * ssj[(q==0)?c0:c1]);
            cr = fminf(fmaxf(cr, -1.0f), 1.0f);
            split3(cr, &sv[6][p][q], &sv[7][p][q], &sv[8][p][q]);
        }
    }

    // direct writes (I, J)
    #pragma unroll
    for (int m = 0; m < 9; m++) {
        #pragma unroll
        for (int p = 0; p < 2; p++) {
            #pragma unroll
            for (int q = 0; q < 2; q++) {
                int I = i0 + r0 + p;
                int J = j0 + ((q == 0) ? c0 : c1);
                Gm[m][(size_t)I * NTOK + J] = sv[m][p][q];
            }
        }
    }

    // mirrored writes (J, I) via one smem transpose stage
    if (bi != bj) {
        #pragma unroll
        for (int m = 0; m < 9; m++) {
            tb[m][c0][r0] = sv[m][0][0];
            tb[m][c0][r1] = sv[m][1][0];
            tb[m][c1][r0] = sv[m][0][1];
            tb[m][c1][r1] = sv[m][1][1];
        }
        __syncthreads();
        int wr = tid >> 3, wc = (tid & 7) * 4;
        #pragma unroll
        for (int m = 0; m < 9; m++) {
            uint2 v = *(const uint2*)&tb[m][wr][wc];
            *(uint2*)(Gm[m] + (size_t)(j0 + wr) * NTOK + i0 + wc) = v;
        }
    }
}

// ---------------- bf16x6 GEMM via mma.sync (HMMA): D = A * B^T ----------------
#define KC 32
#define ROWB 80
#define TILEB (128*ROWB)
#define STAGEB (6*TILEB)
#define GSMEM (2*STAGEB)

#define LDSM4(r, a) \
    asm volatile("ldmatrix.sync.aligned.m8n8.x4.shared.b16 {%0,%1,%2,%3}, [%4];" \
        : "=r"((r)[0]), "=r"((r)[1]), "=r"((r)[2]), "=r"((r)[3]) : "r"(a))

#define MMA16816(d, a, b0r, b1r) \
    asm volatile("mma.sync.aligned.m16n8k16.row.col.f32.bf16.bf16.f32 " \
        "{%0,%1,%2,%3}, {%4,%5,%6,%7}, {%8,%9}, {%0,%1,%2,%3};" \
        : "+f"((d)[0]), "+f"((d)[1]), "+f"((d)[2]), "+f"((d)[3]) \
        : "r"((a)[0]), "r"((a)[1]), "r"((a)[2]), "r"((a)[3]), "r"(b0r), "r"(b1r))

__global__ __launch_bounds__(256, 1) void gemm_mma(int which) {
    extern __shared__ __align__(128) char dsm[];
    uint32_t sb = s2u(dsm);
    int tid = threadIdx.x, lane = tid & 31, wid = tid >> 5;
    int wm = wid >> 2, wn = wid & 3;   // warp tile 64x32, grid 2x4
    size_t boff = (size_t)blockIdx.z * SS;
    const __nv_bfloat16* mats[6];
    if (which == 0) {
        mats[0]=g_e0+boff; mats[1]=g_e1+boff; mats[2]=g_e2+boff;
        mats[3]=g_h0+boff; mats[4]=g_h1+boff; mats[5]=g_h2+boff;
    } else {
        mats[0]=g_a0+boff; mats[1]=g_a1+boff; mats[2]=g_a2+boff;
        mats[3]=g_r0+boff; mats[4]=g_r1+boff; mats[5]=g_r2+boff;
    }
    float* C = (which == 0 ? g_L : g_W) + boff;
    int rowBase = blockIdx.y * 128, colBase = blockIdx.x * 128;

    float acc[4][4][4];
    #pragma unroll
    for (int i = 0; i < 4; i++)
        #pragma unroll
        for (int j = 0; j < 4; j++)
            #pragma unroll
            for (int k = 0; k < 4; k++) acc[i][j][k] = 0.0f;

    unsigned aRowOff = (unsigned)(wm*64 + (lane & 15)) * ROWB + ((lane >> 4) << 4);
    unsigned bRowOff = (unsigned)(wn*32 + (lane & 7) + ((lane >> 4) << 3)) * ROWB
                     + (((lane >> 3) & 1) << 4);

#define LOADSTAGE(st, k0) do { \
    unsigned _so = sb + (unsigned)(st)*STAGEB; \
    _Pragma("unroll") \
    for (int i = 0; i < 12; i++) { \
        int g = i * 256 + tid; \
        int mat = g >> 9, idx = g & 511; \
        int row = idx >> 2, c8 = idx & 3; \
        int rb = (mat < 3) ? rowBase : colBase; \
        const __nv_bfloat16* gp = mats[mat] + (size_t)(rb + row) * NTOK + (k0) + c8*8; \
        unsigned sa = _so + mat*TILEB + row*ROWB + c8*16; \
        asm volatile("cp.async.cg.shared.global [%0], [%1], 16;" :: "r"(sa), "l"(gp)); \
    } \
    asm volatile("cp.async.commit_group;"); \
} while(0)

    LOADSTAGE(0, 0);

    const int pa[6] = {0,0,1,0,1,2}, pb[6] = {0,1,0,2,1,0};

    for (int t = 0; t < 32; t++) {
        if (t < 31) {
            LOADSTAGE((t + 1) & 1, (t + 1) * KC);
            asm volatile("cp.async.wait_group 1;");
        } else {
            asm volatile("cp.async.wait_group 0;");
        }
        __syncthreads();
        unsigned stoff = sb + (unsigned)(t & 1) * STAGEB;
        #pragma unroll
        for (int kf = 0; kf < 2; kf++) {
            uint32_t af[3][4][4];
            uint32_t bf[3][2][4];
            #pragma unroll
            for (int s = 0; s < 3; s++) {
                #pragma unroll
                for (int mf = 0; mf < 4; mf++)
                    LDSM4(af[s][mf], stoff + s*TILEB + aRowOff + mf*(16*ROWB) + kf*32);
                #pragma unroll
                for (int np = 0; np < 2; np++)
                    LDSM4(bf[s][np], stoff + (3+s)*TILEB + bRowOff + np*(16*ROWB) + kf*32);
            }
            #pragma unroll
            for (int p = 0; p < 6; p++) {
                int sa = pa[p], sbp = pb[p];
                #pragma unroll
                for (int mf = 0; mf < 4; mf++) {
                    MMA16816(acc[mf][0], af[sa][mf], bf[sbp][0][0], bf[sbp][0][1]);
                    MMA16816(acc[mf][1], af[sa][mf], bf[sbp][0][2], bf[sbp][0][3]);
                    MMA16816(acc[mf][2], af[sa][mf], bf[sbp][1][0], bf[sbp][1][1]);
                    MMA16816(acc[mf][3], af[sa][mf], bf[sbp][1][2], bf[sbp][1][3]);
                }
            }
        }
        __syncthreads();
    }

    int r0 = rowBase + wm * 64 + (lane >> 2);
    int c0 = colBase + wn * 32 + (lane & 3) * 2;
    #pragma unroll
    for (int mf = 0; mf < 4; mf++) {
        #pragma unroll
        for (int nb = 0; nb < 4; nb++) {
            float* base = C + (size_t)(r0 + mf * 16) * NTOK + c0 + nb * 8;
            *(float2*)base = make_float2(acc[mf][nb][0], acc[mf][nb][1]);
            *(float2*)(base + 8 * NTOK) = make_float2(acc[mf][nb][2], acc[mf][nb][3]);
        }
    }

    // ---- fused selection histogram (gemm2 only) ----
    if (which == 1) {
        unsigned* hist = (unsigned*)dsm;
        __syncthreads();
        for (int i = tid; i < 4096; i += 256) hist[i] = 0;
        __syncthreads();
        #pragma unroll
        for (int mf = 0; mf < 4; mf++)
            #pragma unroll
            for (int nb = 0; nb < 4; nb++)
                #pragma unroll
                for (int k = 0; k < 4; k++)
                    atomicAdd(&hist[fkey(acc[mf][nb][k]) >> 20], 1u);
        __syncthreads();
        int b = blockIdx.z;
        for (int i = tid; i < 4096; i += 256)
            if (hist[i]) atomicAdd(&g_h12[b][i], hist[i]);
    }
#undef LOADSTAGE
}

// ---------------- row softmax of 0.125*L -> attn bf16 splits ----------------
__global__ void softmax_rows() {
    int b = blockIdx.y, row = blockIdx.x;
    size_t base = (size_t)b * SS + (size_t)row * NTOK;
    float* L = g_L + base;
    int tid = threadIdx.x;  // 256
    float v[4];
    #pragma unroll
    for (int i = 0; i < 4; i++) v[i] = L[tid + i * 256] * 0.125f;
    float m = fmaxf(fmaxf(v[0], v[1]), fmaxf(v[2], v[3]));
    __shared__ float red[256];
    red[tid] = m; __syncthreads();
    for (int s = 128; s; s >>= 1) { if (tid < s) red[tid] = fmaxf(red[tid], red[tid + s]); __syncthreads(); }
    m = red[0]; __syncthreads();
    float e[4], sm = 0.0f;
    #pragma unroll
    for (int i = 0; i < 4; i++) { e[i] = expf(v[i] - m); sm += e[i]; }
    red[tid] = sm; __syncthreads();
    for (int s = 128; s; s >>= 1) { if (tid < s) red[tid] += red[tid + s]; __syncthreads(); }
    sm = red[0];
    #pragma unroll
    for (int i = 0; i < 4; i++) {
        size_t o = base + tid + i * 256;
        split3(e[i] / sm, g_a0 + o, g_a1 + o, g_a2 + o);
    }
}

// ---------------- top-k selection ----------------
__global__ void sel_scan12() {   // 1 block of 256 per batch
    int b = blockIdx.x, tid = threadIdx.x;
    __shared__ unsigned csum[256];
    unsigned s = 0;
    for (int k = 0; k < 16; k++) s += g_h12[b][tid * 16 + k];
    csum[tid] = s;
    __syncthreads();
    if (tid == 0) {
        unsigned acc = 0; int c = 255;
        for (; c >= 0; c--) { if (acc + csum[c] >= (unsigned)KSEL) break; acc += csum[c]; }
        int bin = c * 16 + 15;
        for (;; bin--) { unsigned ct = g_h12[b][bin]; if (acc + ct >= (unsigned)KSEL) break; acc += ct; }
        g_s3[b].P12 = (unsigned)bin;
        g_s3[b].kneed = (unsigned)KSEL - acc;
    }
}

__global__ void sel_gather12() {
    int b = blockIdx.y;
    unsigned P = g_s3[b].P12;
    const float4* W = (const float4*)(g_W + (size_t)b * SS);
    for (int i = blockIdx.x * blockDim.x + threadIdx.x; i < SS/4; i += gridDim.x * blockDim.x) {
        float4 v = W[i];
        unsigned base = i * 4;
        float vv[4] = {v.x, v.y, v.z, v.w};
        #pragma unroll
        for (int j = 0; j < 4; j++) {
            unsigned u = fkey(vv[j]);
            if ((u >> 20) == P) {
                unsigned pos = atomicAdd(&g_s3[b].ncand, 1u);
                g_cand[b][pos] = ((unsigned long long)u << 32) | (base + j);
            }
        }
    }
}

__global__ void sel_finish() {  // 1 block of 1024 per batch
    int b = blockIdx.x, tid = threadIdx.x;
    __shared__ unsigned h[256];
    __shared__ unsigned s_prefix, s_kneed;
    unsigned n = g_s3[b].ncand;
    if (tid == 0) { s_prefix = 0; s_kneed = g_s3[b].kneed; }
    __syncthreads();
    const int shs[3] = {12, 4, 0};
    const unsigned wids[3] = {256, 256, 16};
    #pragma unroll
    for (int lvl = 0; lvl < 3; lvl++) {
        int sh = shs[lvl];
        unsigned w = wids[lvl];
        unsigned pmask = (lvl == 0) ? 0u : (0xFFFFFu << (shs[lvl-1]));
        if (tid < w) h[tid] = 0;
        __syncthreads();
        unsigned pfx = s_prefix;
        for (unsigned i = tid; i < n; i += 1024) {
            unsigned low = ((unsigned)(g_cand[b][i] >> 32)) & 0xFFFFFu;
            if ((low & pmask) == pfx) atomicAdd(&h[(low >> sh) & (w - 1)], 1u);
        }
        __syncthreads();
        if (tid == 0) {
            unsigned kneed = s_kneed;
            int bin = (int)w - 1;
            for (; bin >= 0; bin--) { if (kneed <= h[bin]) break; kneed -= h[bin]; }
            s_prefix = pfx | ((unsigned)bin << sh);
            s_kneed = kneed;
        }
        __syncthreads();
    }
    unsigned T = (g_s3[b].P12 << 20) | s_prefix;
    if (tid == 0) s_prefix = 0;
    __syncthreads();
    #pragma unroll
    for (int lvl = 0; lvl < 3; lvl++) {
        int sh = shs[lvl];
        unsigned w = wids[lvl];
        unsigned pmask = (lvl == 0) ? 0u : (0xFFFFFu << (shs[lvl-1]));
        if (tid < w) h[tid] = 0;
        __syncthreads();
        unsigned pfx = s_prefix;
        for (unsigned i = tid; i < n; i += 1024) {
            unsigned long long cv = g_cand[b][i];
            unsigned key = (unsigned)(cv >> 32);
            unsigned idx = (unsigned)cv;
            if (key == T && (idx & pmask) == pfx) atomicAdd(&h[(idx >> sh) & (w - 1)], 1u);
        }
        __syncthreads();
        if (tid == 0) {
            unsigned kneed = s_kneed;
            int bin = (int)w - 1;
            for (; bin >= 0; bin--) { if (kneed <= h[bin]) break; kneed -= h[bin]; }
            s_prefix = pfx | ((unsigned)bin << sh);
            s_kneed = kneed;
        }
        __syncthreads();
    }
    if (tid == 0) { g_s3[b].T = T; g_s3[b].idxT = s_prefix; }
}

__global__ void mask_write(float* __restrict__ out) {
    int b = blockIdx.y;
    unsigned base = (blockIdx.x * 1024 + threadIdx.x) * 4;
    unsigned T = g_s3[b].T;
    unsigned idxT = g_s3[b].idxT;
    const float4 v = *(const float4*)(g_W + (size_t)b * SS + base);
    float r[4]; const float vv[4] = {v.x, v.y, v.z, v.w};
    #pragma unroll
    for (int j = 0; j < 4; j++) {
        unsigned u = fkey(vv[j]);
        r[j] = (u > T || (u == T && base + j >= idxT)) ? 1.0f : 0.0f;
    }
    *(float4*)(out + (size_t)b * SS + base) = make_float4(r[0], r[1], r[2], r[3]);
}

// ---------------- launcher ----------------
extern "C" void kernel_launch(void* const* d_in, const int* in_sizes, int n_in,
                              void* d_out, int out_size) {
    const float* x = (const float*)d_in[0];
    float* out = (float*)d_out;

    cudaFuncSetAttribute(gemm_mma, cudaFuncAttributeMaxDynamicSharedMemorySize, GSMEM);

    pairwise<<<dim3(528, 1, BATCH), 256>>>(x);
    gemm_mma<<<dim3(8, 8, BATCH), 256, GSMEM>>>(0);
    softmax_rows<<<dim3(NTOK, BATCH), 256>>>();
    gemm_mma<<<dim3(8, 8, BATCH), 256, GSMEM>>>(1);

    sel_scan12<<<BATCH, 256>>>();
    sel_gather12<<<dim3(128, BATCH), 256>>>();
    sel_finish<<<BATCH, 1024>>>();
    mask_write<<<dim3(SS / 4096, BATCH), 1024>>>(out);
}